// round 11
// baseline (speedup 1.0000x reference)
#include <cuda_runtime.h>
#include <cuda_fp16.h>
#include <math.h>
#include <cstdint>

#define NN 50000
#define NE 800000
#define H  64
#define ND 128

__device__ float g_xb[2][NN * H];
__device__ float g_agg[NN * H];              // PERMUTED cols
__device__ float g_ps[NN * H];               // permuted: [node][tig*16 + nt*2 + {0,1}]
__device__ float g_pd[NN * H];
__device__ unsigned g_t[3][(size_t)NE * 32]; // T_l = e@W1e_l, fp16 A-fragment order
__device__ unsigned g_xf[NN * 32];           // x fp16 (2 cols/word)

typedef unsigned long long ull;

__device__ __forceinline__ uint32_t smem_u32(const void* p) {
    uint32_t a;
    asm("{ .reg .u64 t; cvta.to.shared.u64 t, %1; cvt.u32.u64 %0, t; }" : "=r"(a) : "l"(p));
    return a;
}

#define LDSM4(r, addr) \
    asm volatile("ldmatrix.sync.aligned.m8n8.x4.shared.b16 {%0,%1,%2,%3}, [%4];" \
        : "=r"((r)[0]), "=r"((r)[1]), "=r"((r)[2]), "=r"((r)[3]) : "r"(addr))

#define MMA16816(c, a, b0v, b1v) \
    asm volatile("mma.sync.aligned.m16n8k16.row.col.f32.f16.f16.f32 " \
        "{%0,%1,%2,%3},{%4,%5,%6,%7},{%8,%9},{%0,%1,%2,%3};" \
        : "+f"((c)[0]), "+f"((c)[1]), "+f"((c)[2]), "+f"((c)[3]) \
        : "r"((a)[0]), "r"((a)[1]), "r"((a)[2]), "r"((a)[3]), "r"(b0v), "r"(b1v))

__device__ __forceinline__ void h_split(float v, __half& h, __half& l) {
    h = __float2half_rn(v);
    l = __float2half_rn(v - __half2float(h));
}
__device__ __forceinline__ unsigned pack_h2(float a, float b) {
    __half2 t = __floats2half2_rn(a, b);
    return *reinterpret_cast<unsigned*>(&t);
}
__device__ __forceinline__ float2 h2f(unsigned u) {
    return __half22float2(*reinterpret_cast<__half2*>(&u));
}

// ============================================================
// k_pre: Ps = x@W1s + b1 (permuted), Pd = x@W1d; zeroes g_agg
// ============================================================
#define PBSH 0
#define PBSL 9216
#define PBDH 18432
#define PBDL 27648
#define PBIAS 36864
#define PA 37120
#define PRE_SMEM (37120 + 8 * 2304)

__global__ void __launch_bounds__(256) k_pre(const float* __restrict__ W1,
                                             const float* __restrict__ b1) {
    extern __shared__ char sm[];
    const uint32_t smb = smem_u32(sm);
    int tid = threadIdx.x, lane = tid & 31, wid = tid >> 5;

    for (int i = tid; i < 64 * 64; i += blockDim.x) {
        int k = i >> 6, n = i & 63;
        __half h, l;
        h_split(W1[k * 64 + n], h, l);
        ((__half*)(sm + PBSH))[n * 72 + k] = h;
        ((__half*)(sm + PBSL))[n * 72 + k] = l;
        h_split(W1[(128 + k) * 64 + n], h, l);
        ((__half*)(sm + PBDH))[n * 72 + k] = h;
        ((__half*)(sm + PBDL))[n * 72 + k] = l;
    }
    if (tid < 64) ((float*)(sm + PBIAS))[tid] = b1[tid];
    __syncthreads();

    const float* b1s = (const float*)(sm + PBIAS);
    const int tig = lane & 3, gid = lane >> 2;
    const uint32_t aRow = smb + PA + wid * 2304 + (lane & 15) * 144 + (lane & 16);
    const uint32_t bRow  = ((lane & 7) + ((lane & 16) >> 1));
    const uint32_t bsH = smb + PBSH + bRow * 144 + (lane & 8) * 2;
    const uint32_t bsL = bsH + (PBSL - PBSH);
    const uint32_t bdH = smb + PBDH + bRow * 144 + (lane & 8) * 2;
    const uint32_t bdL = bdH + (PBDL - PBDH);
    char* aRowPtr = sm + PA + wid * 2304;

    int gw = blockIdx.x * 8 + wid;
    int nw = gridDim.x * 8;
    for (int chunk = gw; chunk < NN / 16; chunk += nw) {
        int base16 = chunk * 16;
        #pragma unroll 4
        for (int t = 0; t < 16; t++)
            ((unsigned*)(aRowPtr + t * 144))[lane] = g_xf[(base16 + t) * 32 + lane];
        __syncwarp();

        float as[8][4], ad[8][4];
        #pragma unroll
        for (int n = 0; n < 8; n++)
            #pragma unroll
            for (int j = 0; j < 4; j++) { as[n][j] = 0.f; ad[n][j] = 0.f; }

        #pragma unroll
        for (int kt = 0; kt < 4; kt++) {
            uint32_t ah[4];
            LDSM4(ah, aRow + kt * 32);
            #pragma unroll
            for (int ng = 0; ng < 4; ng++) {
                uint32_t bh[4], bl[4];
                LDSM4(bh, bsH + ng * 16 * 144 + kt * 32);
                LDSM4(bl, bsL + ng * 16 * 144 + kt * 32);
                MMA16816(as[2 * ng],     ah, bh[0], bh[1]);
                MMA16816(as[2 * ng],     ah, bl[0], bl[1]);
                MMA16816(as[2 * ng + 1], ah, bh[2], bh[3]);
                MMA16816(as[2 * ng + 1], ah, bl[2], bl[3]);
                LDSM4(bh, bdH + ng * 16 * 144 + kt * 32);
                LDSM4(bl, bdL + ng * 16 * 144 + kt * 32);
                MMA16816(ad[2 * ng],     ah, bh[0], bh[1]);
                MMA16816(ad[2 * ng],     ah, bl[0], bl[1]);
                MMA16816(ad[2 * ng + 1], ah, bh[2], bh[3]);
                MMA16816(ad[2 * ng + 1], ah, bl[2], bl[3]);
            }
        }

        int n0 = base16 + gid, n1 = base16 + gid + 8;
        #pragma unroll
        for (int nt = 0; nt < 8; nt++) {
            float2 bb = *(const float2*)(b1s + nt * 8 + 2 * tig);
            int c = nt * 8 + 2 * tig;
            int pc = tig * 16 + nt * 2;
            *(float2*)(g_ps + (size_t)n0 * H + pc) = make_float2(as[nt][0] + bb.x, as[nt][1] + bb.y);
            *(float2*)(g_ps + (size_t)n1 * H + pc) = make_float2(as[nt][2] + bb.x, as[nt][3] + bb.y);
            *(float2*)(g_pd + (size_t)n0 * H + pc) = make_float2(ad[nt][0], ad[nt][1]);
            *(float2*)(g_pd + (size_t)n1 * H + pc) = make_float2(ad[nt][2], ad[nt][3]);
            *(float2*)(g_agg + (size_t)n0 * H + c) = make_float2(0.f, 0.f);
            *(float2*)(g_agg + (size_t)n1 * H + c) = make_float2(0.f, 0.f);
        }
        __syncwarp();
    }
}

// ============================================================
// k_msg_mma: layer-2 only; T from global (A-fragment order)
// ============================================================
#define MB2H 0
#define MB2L 9216
#define MBIAS 18432
#define MSG_SMEM 18944

__global__ void __launch_bounds__(256, 2) k_msg_mma(const int* __restrict__ ei,
        const float* __restrict__ W2, const float* __restrict__ b2, int layer) {
    extern __shared__ char sm[];
    const uint32_t smb = smem_u32(sm);
    int tid = threadIdx.x, lane = tid & 31, wid = tid >> 5;

    for (int i = tid; i < 64 * 64; i += blockDim.x) {
        int k = i >> 6, n = i & 63;
        __half h, l; h_split(W2[k * 64 + n], h, l);
        ((__half*)(sm + MB2H))[n * 72 + k] = h;
        ((__half*)(sm + MB2L))[n * 72 + k] = l;
    }
    if (tid < 64) ((float*)(sm + MBIAS))[tid] = b2[tid];
    __syncthreads();

    const float* b2s = (const float*)(sm + MBIAS);
    const int tig = lane & 3, gid = lane >> 2;
    const uint32_t bRow  = ((lane & 7) + ((lane & 16) >> 1));
    const uint32_t b2H = smb + MB2H + bRow * 144 + (lane & 8) * 2;
    const uint32_t b2L = b2H + (MB2L - MB2H);

    const uint4* t4 = (const uint4*)g_t[layer];
    const int NCH = NE / 16;
    int gw = blockIdx.x * 8 + wid;
    int nw = gridDim.x * 8;

    for (int chunk = gw; chunk < NCH; chunk += nw) {
        int base16 = chunk * 16;
        int s = 0, d = 0;
        if (lane < 16) { s = ei[base16 + lane]; d = ei[NE + base16 + lane]; }
        int s0 = __shfl_sync(0xffffffffu, s, gid), s1 = __shfl_sync(0xffffffffu, s, gid + 8);
        int d0 = __shfl_sync(0xffffffffu, d, gid), d1 = __shfl_sync(0xffffffffu, d, gid + 8);

        // T fragments straight from global (4 x LDG.128)
        uint4 A[4];
        #pragma unroll
        for (int kt = 0; kt < 4; kt++)
            A[kt] = __ldg(t4 + (size_t)chunk * 128 + kt * 32 + lane);

        // Ps/Pd gathers (permuted fp32; 64B contiguous per lane per row)
        float4 P0[4], P1[4], Q0[4], Q1[4];
        {
            const float4* a0p = (const float4*)(g_ps + (size_t)s0 * H + tig * 16);
            const float4* a1p = (const float4*)(g_ps + (size_t)s1 * H + tig * 16);
            const float4* c0p = (const float4*)(g_pd + (size_t)d0 * H + tig * 16);
            const float4* c1p = (const float4*)(g_pd + (size_t)d1 * H + tig * 16);
            #pragma unroll
            for (int m = 0; m < 4; m++) {
                P0[m] = __ldg(a0p + m); P1[m] = __ldg(a1p + m);
                Q0[m] = __ldg(c0p + m); Q1[m] = __ldg(c1p + m);
            }
        }

        // layer 2 fused per kt: hidden = relu(T + Ps + Pd) -> a2 frags -> MMAs
        float acc2[8][4];
        #pragma unroll
        for (int n = 0; n < 8; n++)
            #pragma unroll
            for (int j = 0; j < 4; j++) acc2[n][j] = 0.f;

        #pragma unroll
        for (int kt = 0; kt < 4; kt++) {
            uint32_t a2[4];
            {
                float2 t0 = h2f(A[kt].x);   // row gid,   nt=2kt
                float2 t1 = h2f(A[kt].y);   // row gid+8, nt=2kt
                float2 t2 = h2f(A[kt].z);   // row gid,   nt=2kt+1
                float2 t3 = h2f(A[kt].w);   // row gid+8, nt=2kt+1
                a2[0] = pack_h2(fmaxf(t0.x + P0[kt].x + Q0[kt].x, 0.f),
                                fmaxf(t0.y + P0[kt].y + Q0[kt].y, 0.f));
                a2[1] = pack_h2(fmaxf(t1.x + P1[kt].x + Q1[kt].x, 0.f),
                                fmaxf(t1.y + P1[kt].y + Q1[kt].y, 0.f));
                a2[2] = pack_h2(fmaxf(t2.x + P0[kt].z + Q0[kt].z, 0.f),
                                fmaxf(t2.y + P0[kt].w + Q0[kt].w, 0.f));
                a2[3] = pack_h2(fmaxf(t3.x + P1[kt].z + Q1[kt].z, 0.f),
                                fmaxf(t3.y + P1[kt].w + Q1[kt].w, 0.f));
            }
            #pragma unroll
            for (int ng = 0; ng < 4; ng++) {
                uint32_t bh[4], bl[4];
                LDSM4(bh, b2H + ng * 16 * 144 + kt * 32);
                LDSM4(bl, b2L + ng * 16 * 144 + kt * 32);
                MMA16816(acc2[2 * ng],     a2, bh[0], bh[1]);
                MMA16816(acc2[2 * ng],     a2, bl[0], bl[1]);
                MMA16816(acc2[2 * ng + 1], a2, bh[2], bh[3]);
                MMA16816(acc2[2 * ng + 1], a2, bl[2], bl[3]);
            }
        }

        // epilogue: permuted agg cols -> red.v4
        float* plo = g_agg + (size_t)d0 * H + tig * 4;
        float* phi = g_agg + (size_t)d1 * H + tig * 4;
        #pragma unroll
        for (int m = 0; m < 4; m++) {
            float2 be = *(const float2*)(b2s + (2 * m) * 8 + 2 * tig);
            float2 bo = *(const float2*)(b2s + (2 * m + 1) * 8 + 2 * tig);
            float e0 = acc2[2 * m][0] + be.x, e1 = acc2[2 * m][1] + be.y;
            float o0 = acc2[2 * m + 1][0] + bo.x, o1 = acc2[2 * m + 1][1] + bo.y;
            asm volatile("red.global.add.v4.f32 [%0], {%1,%2,%3,%4};"
                :: "l"(plo + m * 16), "f"(e0), "f"(e1), "f"(o0), "f"(o1) : "memory");
            float e2 = acc2[2 * m][2] + be.x, e3 = acc2[2 * m][3] + be.y;
            float o2 = acc2[2 * m + 1][2] + bo.x, o3 = acc2[2 * m + 1][3] + bo.y;
            asm volatile("red.global.add.v4.f32 [%0], {%1,%2,%3,%4};"
                :: "l"(phi + m * 16), "f"(e2), "f"(e3), "f"(o2), "f"(o3) : "memory");
        }
        __syncwarp();
    }
}

// ============================================================
// k_upd_mma: unchanged from R10
// ============================================================
#define UB1H 0
#define UB1L 17408
#define UB2H 34816
#define UB2L 44032
#define UBIAS 53248
#define UA 53760
#define UPD_SMEM (53760 + 8 * 4352)

__global__ void __launch_bounds__(256, 2) k_upd_mma(
        const float* __restrict__ W1, const float* __restrict__ b1,
        const float* __restrict__ W2, const float* __restrict__ b2,
        int si, int di) {
    extern __shared__ char sm[];
    const uint32_t smb = smem_u32(sm);
    int tid = threadIdx.x, lane = tid & 31, wid = tid >> 5;

    for (int i = tid; i < 128 * 64; i += blockDim.x) {
        int k = i >> 6, n = i & 63;
        __half h, l; h_split(W1[i], h, l);
        ((__half*)(sm + UB1H))[n * 136 + k] = h;
        ((__half*)(sm + UB1L))[n * 136 + k] = l;
    }
    for (int i = tid; i < 64 * 64; i += blockDim.x) {
        int k = i >> 6, n = i & 63;
        __half h, l; h_split(W2[i], h, l);
        ((__half*)(sm + UB2H))[n * 72 + k] = h;
        ((__half*)(sm + UB2L))[n * 72 + k] = l;
    }
    if (tid < 64) {
        ((float*)(sm + UBIAS))[tid] = b1[tid];
        ((float*)(sm + UBIAS + 256))[tid] = b2[tid];
    }
    __syncthreads();

    const float* b1s = (const float*)(sm + UBIAS);
    const float* b2s = (const float*)(sm + UBIAS + 256);
    float* xd = g_xb[di];

    const int tig = lane & 3, gid = lane >> 2;
    const int wagg = (2 * (lane >> 3) + (lane & 1)) * 4 + ((lane >> 1) & 3);
    const uint32_t aRow = smb + UA + wid * 4352 + (lane & 15) * 272 + (lane & 16);
    const uint32_t bRow  = ((lane & 7) + ((lane & 16) >> 1));
    const uint32_t b1AddrH = smb + UB1H + bRow * 272 + (lane & 8) * 2;
    const uint32_t b1AddrL = b1AddrH + (UB1L - UB1H);
    const uint32_t b2AddrH = smb + UB2H + bRow * 144 + (lane & 8) * 2;
    const uint32_t b2AddrL = b2AddrH + (UB2L - UB2H);
    char* aRowPtr = sm + UA + wid * 4352;

    int gw = blockIdx.x * 8 + wid;
    int nw = gridDim.x * 8;
    for (int chunk = gw; chunk < NN / 16; chunk += nw) {
        int base16 = chunk * 16;
        #pragma unroll 4
        for (int t = 0; t < 16; t++) {
            int n = base16 + t;
            float2* agp = (float2*)(g_agg + (size_t)n * H) + lane;
            float2 ag = *agp;
            *agp = make_float2(0.f, 0.f);
            char* rp = aRowPtr + t * 272;
            ((unsigned*)rp)[lane]         = g_xf[n * 32 + lane];
            ((unsigned*)(rp + 128))[wagg] = pack_h2(ag.x, ag.y);
        }
        __syncwarp();

        float acc[8][4];
        #pragma unroll
        for (int n = 0; n < 8; n++)
            #pragma unroll
            for (int j = 0; j < 4; j++) acc[n][j] = 0.f;

        #pragma unroll 2
        for (int kt = 0; kt < 8; kt++) {
            uint32_t ah[4];
            LDSM4(ah, aRow + kt * 32);
            #pragma unroll
            for (int ng = 0; ng < 4; ng++) {
                uint32_t bh[4], bl[4];
                LDSM4(bh, b1AddrH + ng * 16 * 272 + kt * 32);
                LDSM4(bl, b1AddrL + ng * 16 * 272 + kt * 32);
                MMA16816(acc[2 * ng],     ah, bh[0], bh[1]);
                MMA16816(acc[2 * ng],     ah, bl[0], bl[1]);
                MMA16816(acc[2 * ng + 1], ah, bh[2], bh[3]);
                MMA16816(acc[2 * ng + 1], ah, bl[2], bl[3]);
            }
        }

        float acc2[8][4];
        #pragma unroll
        for (int n = 0; n < 8; n++)
            #pragma unroll
            for (int j = 0; j < 4; j++) acc2[n][j] = 0.f;

        #pragma unroll
        for (int kt = 0; kt < 4; kt++) {
            uint32_t a2[4];
            #pragma unroll
            for (int j = 0; j < 2; j++) {
                int nt = kt * 2 + j;
                float2 bb = *(const float2*)(b1s + nt * 8 + 2 * tig);
                float v0 = fmaxf(acc[nt][0] + bb.x, 0.f);
                float v1 = fmaxf(acc[nt][1] + bb.y, 0.f);
                float v2 = fmaxf(acc[nt][2] + bb.x, 0.f);
                float v3 = fmaxf(acc[nt][3] + bb.y, 0.f);
                a2[2 * j]     = pack_h2(v0, v1);
                a2[2 * j + 1] = pack_h2(v2, v3);
            }
            #pragma unroll
            for (int ng = 0; ng < 4; ng++) {
                uint32_t bh[4], bl[4];
                LDSM4(bh, b2AddrH + ng * 16 * 144 + kt * 32);
                LDSM4(bl, b2AddrL + ng * 16 * 144 + kt * 32);
                MMA16816(acc2[2 * ng],     a2, bh[0], bh[1]);
                MMA16816(acc2[2 * ng],     a2, bl[0], bl[1]);
                MMA16816(acc2[2 * ng + 1], a2, bh[2], bh[3]);
                MMA16816(acc2[2 * ng + 1], a2, bl[2], bl[3]);
            }
        }

        int n0 = base16 + gid, n1 = base16 + gid + 8;
        #pragma unroll
        for (int nt = 0; nt < 8; nt++) {
            float2 bb = *(const float2*)(b2s + nt * 8 + 2 * tig);
            float f0 = acc2[nt][0] + bb.x, f1 = acc2[nt][1] + bb.y;
            float f2 = acc2[nt][2] + bb.x, f3 = acc2[nt][3] + bb.y;
            *(float2*)(xd + (size_t)n0 * H + nt * 8 + 2 * tig) = make_float2(f0, f1);
            *(float2*)(xd + (size_t)n1 * H + nt * 8 + 2 * tig) = make_float2(f2, f3);
            g_xf[n0 * 32 + nt * 4 + tig] = pack_h2(f0, f1);
            g_xf[n1 * 32 + nt * 4 + tig] = pack_h2(f2, f3);
        }
        __syncwarp();
    }
}

// ============================================================
// k_enc_edge_mma: e = ef@We + be, then T_l = e@W1e_l for l=0..2,
//                 written fp16 in MMA A-fragment order
// ============================================================
#define EWH 0
#define EWL 9216
#define ETB 18432                 // 3 layers x (hi,lo) of 9216 each
#define EBIAS 73728
#define EA 73984
#define ENC_SMEM (73984 + 8 * 2304)   // 92416

__global__ void __launch_bounds__(256) k_enc_edge_mma(const float* __restrict__ ef,
        const float* __restrict__ We, const float* __restrict__ be,
        const float* __restrict__ mW1) {
    extern __shared__ char sm[];
    const uint32_t smb = smem_u32(sm);
    int tid = threadIdx.x, lane = tid & 31, wid = tid >> 5;

    for (int i = tid; i < 64 * 64; i += blockDim.x) {
        int k = i >> 6, n = i & 63;
        __half h, l; h_split(We[i], h, l);
        ((__half*)(sm + EWH))[n * 72 + k] = h;
        ((__half*)(sm + EWL))[n * 72 + k] = l;
        #pragma unroll
        for (int lyr = 0; lyr < 3; lyr++) {
            h_split(mW1[((size_t)lyr * 192 + 64 + k) * 64 + n], h, l);
            ((__half*)(sm + ETB + lyr * 18432))[n * 72 + k] = h;
            ((__half*)(sm + ETB + lyr * 18432 + 9216))[n * 72 + k] = l;
        }
    }
    if (tid < 64) ((float*)(sm + EBIAS))[tid] = be[tid];
    __syncthreads();

    const float* bs = (const float*)(sm + EBIAS);
    const int tig = lane & 3;
    const int gi = lane >> 2;
    const uint32_t aRow = smb + EA + wid * 2304 + (lane & 15) * 144 + (lane & 16);
    const uint32_t bRow  = ((lane & 7) + ((lane & 16) >> 1));
    const uint32_t bWH = smb + EWH + bRow * 144 + (lane & 8) * 2;
    const uint32_t bWL = bWH + 9216;
    char* aRowPtr = sm + EA + wid * 2304;

    int gw = blockIdx.x * 8 + wid;
    int nw = gridDim.x * 8;
    for (int chunk = gw; chunk < NE / 16; chunk += nw) {
        int base16 = chunk * 16;
        #pragma unroll 4
        for (int t = 0; t < 16; t++) {
            float2 v = ((const float2*)(ef + (size_t)(base16 + t) * H))[lane];
            ((unsigned*)(aRowPtr + t * 144))[lane] = pack_h2(v.x, v.y);
        }
        __syncwarp();

        // e = ef @ We (fp16 2-term)
        float acc[8][4];
        #pragma unroll
        for (int n = 0; n < 8; n++)
            #pragma unroll
            for (int j = 0; j < 4; j++) acc[n][j] = 0.f;

        #pragma unroll
        for (int kt = 0; kt < 4; kt++) {
            uint32_t ah[4];
            LDSM4(ah, aRow + kt * 32);
            #pragma unroll
            for (int ng = 0; ng < 4; ng++) {
                uint32_t bh[4], bl[4];
                LDSM4(bh, bWH + ng * 16 * 144 + kt * 32);
                LDSM4(bl, bWL + ng * 16 * 144 + kt * 32);
                MMA16816(acc[2 * ng],     ah, bh[0], bh[1]);
                MMA16816(acc[2 * ng],     ah, bl[0], bl[1]);
                MMA16816(acc[2 * ng + 1], ah, bh[2], bh[3]);
                MMA16816(acc[2 * ng + 1], ah, bl[2], bl[3]);
            }
        }

        // e (+bias) -> A fragments (registers), FA2 trick
        uint32_t ea[4][4];
        #pragma unroll
        for (int kt = 0; kt < 4; kt++) {
            #pragma unroll
            for (int j = 0; j < 2; j++) {
                int nt = 2 * kt + j;
                float2 bb = *(const float2*)(bs + nt * 8 + 2 * tig);
                ea[kt][2 * j]     = pack_h2(acc[nt][0] + bb.x, acc[nt][1] + bb.y);
                ea[kt][2 * j + 1] = pack_h2(acc[nt][2] + bb.x, acc[nt][3] + bb.y);
            }
        }

        // T_l = e @ W1e_l, write fp16 A-fragment order
        #pragma unroll
        for (int lyr = 0; lyr < 3; lyr++) {
            const uint32_t bTH = smb + ETB + lyr * 18432 + bRow * 144 + (lane & 8) * 2;
            const uint32_t bTL = bTH + 9216;
            float acc2[8][4];
            #pragma unroll
            for (int n = 0; n < 8; n++)
                #pragma unroll
                for (int j = 0; j < 4; j++) acc2[n][j] = 0.f;

            #pragma unroll
            for (int kt = 0; kt < 4; kt++) {
                #pragma unroll
                for (int ng = 0; ng < 4; ng++) {
                    uint32_t bh[4], bl[4];
                    LDSM4(bh, bTH + ng * 16 * 144 + kt * 32);
                    LDSM4(bl, bTL + ng * 16 * 144 + kt * 32);
                    MMA16816(acc2[2 * ng],     ea[kt], bh[0], bh[1]);
                    MMA16816(acc2[2 * ng],     ea[kt], bl[0], bl[1]);
                    MMA16816(acc2[2 * ng + 1], ea[kt], bh[2], bh[3]);
                    MMA16816(acc2[2 * ng + 1], ea[kt], bl[2], bl[3]);
                }
            }

            unsigned* dt = g_t[lyr] + (size_t)chunk * 512;
            #pragma unroll
            for (int nt = 0; nt < 8; nt++) {
                int idx = (nt >> 1) * 128 + (gi * 4 + tig) * 4 + 2 * (nt & 1);
                dt[idx]     = pack_h2(acc2[nt][0], acc2[nt][1]);   // row gi
                dt[idx + 1] = pack_h2(acc2[nt][2], acc2[nt][3]);   // row gi+8
            }
        }
        __syncwarp();
    }
}

// ============================================================
// k_enc_node: scalar f32x2; writes fp32 x + fp16 x
// ============================================================
__device__ __forceinline__ void ffma2(ull& d, ull a, ull b) {
    asm("fma.rn.f32x2 %0, %1, %2, %0;" : "+l"(d) : "l"(a), "l"(b));
}
__device__ __forceinline__ float fin(ull a, float b) {
    return __uint_as_float((unsigned)a) + __uint_as_float((unsigned)(a >> 32)) + b;
}

__global__ void __launch_bounds__(256) k_enc_node(const float* __restrict__ nf,
        const float* __restrict__ W, const float* __restrict__ b) {
    extern __shared__ float smf[];
    float* Wp   = smf;
    float* winb = Wp + 8320;
    int tid = threadIdx.x;
    for (int i = tid; i < 128 * 64; i += 256) {
        int k = i >> 6, c = i & 63;
        Wp[(c >> 1) * 260 + (k >> 1) * 4 + ((c & 1) << 1) + (k & 1)] = W[i];
    }
    __syncthreads();
    int lane = tid & 31, wid = tid >> 5;
    float2 bb = ((const float2*)b)[lane];
    float* win = winb + wid * 8 * ND;
    const ulonglong2* wl = (const ulonglong2*)(Wp + (size_t)lane * 260);
    int gw = blockIdx.x * 8 + wid;
    int nw = gridDim.x * 8;
    for (int base = gw * 8; base < NN; base += nw * 8) {
        #pragma unroll
        for (int t = 0; t < 8; t++) {
            float4 v = *(const float4*)(nf + (size_t)(base + t) * ND + lane * 4);
            *(float4*)(win + t * ND + lane * 4) = v;
        }
        __syncwarp();
        ull a0[8], a1[8];
        #pragma unroll
        for (int t = 0; t < 8; t++) { a0[t] = 0ull; a1[t] = 0ull; }
        #pragma unroll 4
        for (int c = 0; c < 32; c++) {
            ulonglong2 wA = wl[2 * c];
            ulonglong2 wB = wl[2 * c + 1];
            #pragma unroll
            for (int t = 0; t < 8; t++) {
                ulonglong2 v = ((const ulonglong2*)(win + t * ND))[c];
                ffma2(a0[t], wA.x, v.x); ffma2(a1[t], wA.y, v.x);
                ffma2(a0[t], wB.x, v.y); ffma2(a1[t], wB.y, v.y);
            }
        }
        #pragma unroll
        for (int t = 0; t < 8; t++) {
            float o0 = fin(a0[t], bb.x);
            float o1 = fin(a1[t], bb.y);
            int n = base + t;
            *(float2*)(g_xb[0] + (size_t)n * H + 2 * lane) = make_float2(o0, o1);
            g_xf[n * 32 + lane] = pack_h2(o0, o1);
        }
        __syncwarp();
    }
}

__global__ void k_con(const float* __restrict__ W1, const float* __restrict__ b1,
                      const float* __restrict__ w2, const float* __restrict__ b2,
                      int si, float* __restrict__ out) {
    __shared__ float Ws[H * H];
    __shared__ float bs[H];
    __shared__ float w2s[H];
    __shared__ float xb[8][H];
    __shared__ float b2v;
    int tid = threadIdx.x;
    for (int i = tid; i < H * H; i += blockDim.x) Ws[i] = W1[i];
    if (tid < H) { bs[tid] = b1[tid]; w2s[tid] = w2[tid]; }
    if (tid == 0) b2v = b2[0];
    __syncthreads();
    const float* xs = g_xb[si];
    int lane = tid & 31, wid = tid >> 5;
    int gw = blockIdx.x * 8 + wid;
    int nw = gridDim.x * 8;
    for (int n = gw; n < NN; n += nw) {
        float xv0 = xs[(size_t)n * H + lane];
        float xv1 = xs[(size_t)n * H + lane + 32];
        out[(size_t)n * H + lane]      = xv0;
        out[(size_t)n * H + lane + 32] = xv1;
        xb[wid][lane]      = xv0;
        xb[wid][lane + 32] = xv1;
        __syncwarp();
        float a0 = bs[lane], a1 = bs[lane + 32];
        #pragma unroll 4
        for (int k = 0; k < H; k++) {
            float v = xb[wid][k];
            a0 += v * Ws[k * H + lane];
            a1 += v * Ws[k * H + lane + 32];
        }
        float p = fmaxf(a0, 0.f) * w2s[lane] + fmaxf(a1, 0.f) * w2s[lane + 32];
        #pragma unroll
        for (int o = 16; o; o >>= 1) p += __shfl_xor_sync(0xffffffffu, p, o);
        if (lane == 0)
            out[(size_t)NN * H + n] = 1.f / (1.f + expf(-(p + b2v)));
        __syncwarp();
    }
}

extern "C" void kernel_launch(void* const* d_in, const int* in_sizes, int n_in,
                              void* d_out, int out_size) {
    const float* nf  = (const float*)d_in[0];
    const float* ef  = (const float*)d_in[1];
    const int*   ei  = (const int*)d_in[2];
    const float* enW = (const float*)d_in[3];
    const float* enb = (const float*)d_in[4];
    const float* eeW = (const float*)d_in[5];
    const float* eeb = (const float*)d_in[6];
    const float* mW1 = (const float*)d_in[7];
    const float* mb1 = (const float*)d_in[8];
    const float* mW2 = (const float*)d_in[9];
    const float* mb2 = (const float*)d_in[10];
    const float* uW1 = (const float*)d_in[11];
    const float* ub1 = (const float*)d_in[12];
    const float* uW2 = (const float*)d_in[13];
    const float* ub2 = (const float*)d_in[14];
    const float* cW1 = (const float*)d_in[15];
    const float* cb1 = (const float*)d_in[16];
    const float* cW2 = (const float*)d_in[17];
    const float* cb2 = (const float*)d_in[18];
    float* out = (float*)d_out;

    int dev = 0, smc = 148;
    cudaGetDevice(&dev);
    cudaDeviceGetAttribute(&smc, cudaDevAttrMultiProcessorCount, dev);

    const int ENN_SMEM = (8320 + 8192) * 4;
    cudaFuncSetAttribute(k_pre,          cudaFuncAttributeMaxDynamicSharedMemorySize, PRE_SMEM);
    cudaFuncSetAttribute(k_msg_mma,      cudaFuncAttributeMaxDynamicSharedMemorySize, MSG_SMEM);
    cudaFuncSetAttribute(k_upd_mma,      cudaFuncAttributeMaxDynamicSharedMemorySize, UPD_SMEM);
    cudaFuncSetAttribute(k_enc_edge_mma, cudaFuncAttributeMaxDynamicSharedMemorySize, ENC_SMEM);
    cudaFuncSetAttribute(k_enc_node,     cudaFuncAttributeMaxDynamicSharedMemorySize, ENN_SMEM);

    k_enc_node<<<smc * 2, 256, ENN_SMEM>>>(nf, enW, enb);
    k_enc_edge_mma<<<smc * 2, 256, ENC_SMEM>>>(ef, eeW, eeb, mW1);

    int cur = 0;
    for (int l = 0; l < 3; l++) {
        k_pre<<<smc * 2, 256, PRE_SMEM>>>(mW1 + (size_t)l * 192 * H, mb1 + l * H);
        k_msg_mma<<<smc * 2, 256, MSG_SMEM>>>(ei, mW2 + (size_t)l * H * H, mb2 + l * H, l);
        k_upd_mma<<<smc * 2, 256, UPD_SMEM>>>(uW1 + (size_t)l * 128 * H, ub1 + l * H,
                                              uW2 + (size_t)l * H * H,   ub2 + l * H,
                                              cur, 1 - cur);
        cur = 1 - cur;
    }
    k_con<<<1184, 256>>>(cW1, cb1, cW2, cb2, cur, out);
}

// round 12
// speedup vs baseline: 1.1313x; 1.1313x over previous
#include <cuda_runtime.h>
#include <cuda_fp16.h>
#include <math.h>
#include <cstdint>

#define NN 50000
#define NE 800000
#define H  64
#define ND 128

__device__ float g_xb[2][NN * H];
__device__ float g_agg[NN * H];              // PERMUTED cols
__device__ float g_ps[NN * H];               // permuted: [node][tig*16 + nt*2 + {0,1}]
__device__ float g_pd[NN * H];
__device__ unsigned g_et[(size_t)NE * 32];   // e fp16 in MMA A-fragment order per 16-edge chunk
__device__ unsigned g_xf[NN * 32];           // x fp16 (2 cols/word)

typedef unsigned long long ull;

__device__ __forceinline__ uint32_t smem_u32(const void* p) {
    uint32_t a;
    asm("{ .reg .u64 t; cvta.to.shared.u64 t, %1; cvt.u32.u64 %0, t; }" : "=r"(a) : "l"(p));
    return a;
}

#define LDSM4(r, addr) \
    asm volatile("ldmatrix.sync.aligned.m8n8.x4.shared.b16 {%0,%1,%2,%3}, [%4];" \
        : "=r"((r)[0]), "=r"((r)[1]), "=r"((r)[2]), "=r"((r)[3]) : "r"(addr))

#define MMA16816(c, a, b0v, b1v) \
    asm volatile("mma.sync.aligned.m16n8k16.row.col.f32.f16.f16.f32 " \
        "{%0,%1,%2,%3},{%4,%5,%6,%7},{%8,%9},{%0,%1,%2,%3};" \
        : "+f"((c)[0]), "+f"((c)[1]), "+f"((c)[2]), "+f"((c)[3]) \
        : "r"((a)[0]), "r"((a)[1]), "r"((a)[2]), "r"((a)[3]), "r"(b0v), "r"(b1v))

__device__ __forceinline__ void h_split(float v, __half& h, __half& l) {
    h = __float2half_rn(v);
    l = __float2half_rn(v - __half2float(h));
}
__device__ __forceinline__ unsigned pack_h2(float a, float b) {
    __half2 t = __floats2half2_rn(a, b);
    return *reinterpret_cast<unsigned*>(&t);
}

// ============================================================
// k_pre: Ps = x@W1s + b1 (permuted), Pd = x@W1d; zeroes g_agg
// ============================================================
#define PBSH 0
#define PBSL 9216
#define PBDH 18432
#define PBDL 27648
#define PBIAS 36864
#define PA 37120
#define PRE_SMEM (37120 + 8 * 2304)

__global__ void __launch_bounds__(256) k_pre(const float* __restrict__ W1,
                                             const float* __restrict__ b1) {
    extern __shared__ char sm[];
    const uint32_t smb = smem_u32(sm);
    int tid = threadIdx.x, lane = tid & 31, wid = tid >> 5;

    for (int i = tid; i < 64 * 64; i += blockDim.x) {
        int k = i >> 6, n = i & 63;
        __half h, l;
        h_split(W1[k * 64 + n], h, l);
        ((__half*)(sm + PBSH))[n * 72 + k] = h;
        ((__half*)(sm + PBSL))[n * 72 + k] = l;
        h_split(W1[(128 + k) * 64 + n], h, l);
        ((__half*)(sm + PBDH))[n * 72 + k] = h;
        ((__half*)(sm + PBDL))[n * 72 + k] = l;
    }
    if (tid < 64) ((float*)(sm + PBIAS))[tid] = b1[tid];
    __syncthreads();

    const float* b1s = (const float*)(sm + PBIAS);
    const int tig = lane & 3, gid = lane >> 2;
    const uint32_t aRow = smb + PA + wid * 2304 + (lane & 15) * 144 + (lane & 16);
    const uint32_t bRow  = ((lane & 7) + ((lane & 16) >> 1));
    const uint32_t bsH = smb + PBSH + bRow * 144 + (lane & 8) * 2;
    const uint32_t bsL = bsH + (PBSL - PBSH);
    const uint32_t bdH = smb + PBDH + bRow * 144 + (lane & 8) * 2;
    const uint32_t bdL = bdH + (PBDL - PBDH);
    char* aRowPtr = sm + PA + wid * 2304;

    int gw = blockIdx.x * 8 + wid;
    int nw = gridDim.x * 8;
    for (int chunk = gw; chunk < NN / 16; chunk += nw) {
        int base16 = chunk * 16;
        #pragma unroll 4
        for (int t = 0; t < 16; t++)
            ((unsigned*)(aRowPtr + t * 144))[lane] = g_xf[(base16 + t) * 32 + lane];
        __syncwarp();

        float as[8][4], ad[8][4];
        #pragma unroll
        for (int n = 0; n < 8; n++)
            #pragma unroll
            for (int j = 0; j < 4; j++) { as[n][j] = 0.f; ad[n][j] = 0.f; }

        #pragma unroll
        for (int kt = 0; kt < 4; kt++) {
            uint32_t ah[4];
            LDSM4(ah, aRow + kt * 32);
            #pragma unroll
            for (int ng = 0; ng < 4; ng++) {
                uint32_t bh[4], bl[4];
                LDSM4(bh, bsH + ng * 16 * 144 + kt * 32);
                LDSM4(bl, bsL + ng * 16 * 144 + kt * 32);
                MMA16816(as[2 * ng],     ah, bh[0], bh[1]);
                MMA16816(as[2 * ng],     ah, bl[0], bl[1]);
                MMA16816(as[2 * ng + 1], ah, bh[2], bh[3]);
                MMA16816(as[2 * ng + 1], ah, bl[2], bl[3]);
                LDSM4(bh, bdH + ng * 16 * 144 + kt * 32);
                LDSM4(bl, bdL + ng * 16 * 144 + kt * 32);
                MMA16816(ad[2 * ng],     ah, bh[0], bh[1]);
                MMA16816(ad[2 * ng],     ah, bl[0], bl[1]);
                MMA16816(ad[2 * ng + 1], ah, bh[2], bh[3]);
                MMA16816(ad[2 * ng + 1], ah, bl[2], bl[3]);
            }
        }

        int n0 = base16 + gid, n1 = base16 + gid + 8;
        #pragma unroll
        for (int nt = 0; nt < 8; nt++) {
            float2 bb = *(const float2*)(b1s + nt * 8 + 2 * tig);
            int c = nt * 8 + 2 * tig;
            int pc = tig * 16 + nt * 2;
            *(float2*)(g_ps + (size_t)n0 * H + pc) = make_float2(as[nt][0] + bb.x, as[nt][1] + bb.y);
            *(float2*)(g_ps + (size_t)n1 * H + pc) = make_float2(as[nt][2] + bb.x, as[nt][3] + bb.y);
            *(float2*)(g_pd + (size_t)n0 * H + pc) = make_float2(ad[nt][0], ad[nt][1]);
            *(float2*)(g_pd + (size_t)n1 * H + pc) = make_float2(ad[nt][2], ad[nt][3]);
            *(float2*)(g_agg + (size_t)n0 * H + c) = make_float2(0.f, 0.f);
            *(float2*)(g_agg + (size_t)n1 * H + c) = make_float2(0.f, 0.f);
        }
        __syncwarp();
    }
}

// ============================================================
// k_msg_mma: A from global (fragment order), HI-ONLY weights
// ============================================================
#define MB1H 0
#define MB2H 9216
#define MBIAS 18432
#define MSG_SMEM 18944

__global__ void __launch_bounds__(256, 2) k_msg_mma(const int* __restrict__ ei,
        const float* __restrict__ W1, const float* __restrict__ W2,
        const float* __restrict__ b2) {
    extern __shared__ char sm[];
    const uint32_t smb = smem_u32(sm);
    int tid = threadIdx.x, lane = tid & 31, wid = tid >> 5;

    for (int i = tid; i < 64 * 64; i += blockDim.x) {
        int k = i >> 6, n = i & 63;
        ((__half*)(sm + MB1H))[n * 72 + k] = __float2half_rn(W1[(64 + k) * 64 + n]);
        ((__half*)(sm + MB2H))[n * 72 + k] = __float2half_rn(W2[k * 64 + n]);
    }
    if (tid < 64) ((float*)(sm + MBIAS))[tid] = b2[tid];
    __syncthreads();

    const float* b2s = (const float*)(sm + MBIAS);
    const int tig = lane & 3, gid = lane >> 2;
    const uint32_t bRow  = ((lane & 7) + ((lane & 16) >> 1));
    const uint32_t b1H = smb + MB1H + bRow * 144 + (lane & 8) * 2;
    const uint32_t b2H = smb + MB2H + bRow * 144 + (lane & 8) * 2;

    const uint4* et4 = (const uint4*)g_et;
    const int NCH = NE / 16;
    int gw = blockIdx.x * 8 + wid;
    int nw = gridDim.x * 8;

    for (int chunk = gw; chunk < NCH; chunk += nw) {
        int base16 = chunk * 16;
        int s = 0, d = 0;
        if (lane < 16) { s = ei[base16 + lane]; d = ei[NE + base16 + lane]; }
        int s0 = __shfl_sync(0xffffffffu, s, gid), s1 = __shfl_sync(0xffffffffu, s, gid + 8);
        int d0 = __shfl_sync(0xffffffffu, d, gid), d1 = __shfl_sync(0xffffffffu, d, gid + 8);

        // A fragments straight from global (4 x LDG.128)
        uint4 A[4];
        #pragma unroll
        for (int kt = 0; kt < 4; kt++)
            A[kt] = __ldg(et4 + (size_t)chunk * 128 + kt * 32 + lane);

        // layer 1 (e-term): K=64, hi-only weights
        float acc[8][4];
        #pragma unroll
        for (int n = 0; n < 8; n++)
            #pragma unroll
            for (int j = 0; j < 4; j++) acc[n][j] = 0.f;

        #pragma unroll
        for (int kt = 0; kt < 4; kt++) {
            uint32_t ah[4] = {A[kt].x, A[kt].y, A[kt].z, A[kt].w};
            #pragma unroll
            for (int ng = 0; ng < 4; ng++) {
                uint32_t bh[4];
                LDSM4(bh, b1H + ng * 16 * 144 + kt * 32);
                MMA16816(acc[2 * ng],     ah, bh[0], bh[1]);
                MMA16816(acc[2 * ng + 1], ah, bh[2], bh[3]);
            }
        }

        // Ps/Pd gathers (permuted fp32; 64B contiguous per lane per row)
        float4 P0[4], P1[4], Q0[4], Q1[4];
        {
            const float4* a0p = (const float4*)(g_ps + (size_t)s0 * H + tig * 16);
            const float4* a1p = (const float4*)(g_ps + (size_t)s1 * H + tig * 16);
            const float4* c0p = (const float4*)(g_pd + (size_t)d0 * H + tig * 16);
            const float4* c1p = (const float4*)(g_pd + (size_t)d1 * H + tig * 16);
            #pragma unroll
            for (int m = 0; m < 4; m++) {
                P0[m] = __ldg(a0p + m); P1[m] = __ldg(a1p + m);
                Q0[m] = __ldg(c0p + m); Q1[m] = __ldg(c1p + m);
            }
        }

        // layer 2 fused per kt, hi-only weights
        float acc2[8][4];
        #pragma unroll
        for (int n = 0; n < 8; n++)
            #pragma unroll
            for (int j = 0; j < 4; j++) acc2[n][j] = 0.f;

        #pragma unroll
        for (int kt = 0; kt < 4; kt++) {
            uint32_t a2[4];
            #pragma unroll
            for (int j = 0; j < 2; j++) {
                int nt = 2 * kt + j;
                float pa0 = j ? P0[kt].z : P0[kt].x, pa1 = j ? P0[kt].w : P0[kt].y;
                float qa0 = j ? Q0[kt].z : Q0[kt].x, qa1 = j ? Q0[kt].w : Q0[kt].y;
                float pb0 = j ? P1[kt].z : P1[kt].x, pb1 = j ? P1[kt].w : P1[kt].y;
                float qb0 = j ? Q1[kt].z : Q1[kt].x, qb1 = j ? Q1[kt].w : Q1[kt].y;
                float v0 = fmaxf(acc[nt][0] + pa0 + qa0, 0.f);
                float v1 = fmaxf(acc[nt][1] + pa1 + qa1, 0.f);
                float v2 = fmaxf(acc[nt][2] + pb0 + qb0, 0.f);
                float v3 = fmaxf(acc[nt][3] + pb1 + qb1, 0.f);
                a2[2 * j]     = pack_h2(v0, v1);
                a2[2 * j + 1] = pack_h2(v2, v3);
            }
            #pragma unroll
            for (int ng = 0; ng < 4; ng++) {
                uint32_t bh[4];
                LDSM4(bh, b2H + ng * 16 * 144 + kt * 32);
                MMA16816(acc2[2 * ng],     a2, bh[0], bh[1]);
                MMA16816(acc2[2 * ng + 1], a2, bh[2], bh[3]);
            }
        }

        // epilogue: permuted agg cols -> red.v4
        float* plo = g_agg + (size_t)d0 * H + tig * 4;
        float* phi = g_agg + (size_t)d1 * H + tig * 4;
        #pragma unroll
        for (int m = 0; m < 4; m++) {
            float2 be = *(const float2*)(b2s + (2 * m) * 8 + 2 * tig);
            float2 bo = *(const float2*)(b2s + (2 * m + 1) * 8 + 2 * tig);
            float e0 = acc2[2 * m][0] + be.x, e1 = acc2[2 * m][1] + be.y;
            float o0 = acc2[2 * m + 1][0] + bo.x, o1 = acc2[2 * m + 1][1] + bo.y;
            asm volatile("red.global.add.v4.f32 [%0], {%1,%2,%3,%4};"
                :: "l"(plo + m * 16), "f"(e0), "f"(e1), "f"(o0), "f"(o1) : "memory");
            float e2 = acc2[2 * m][2] + be.x, e3 = acc2[2 * m][3] + be.y;
            float o2 = acc2[2 * m + 1][2] + bo.x, o3 = acc2[2 * m + 1][3] + bo.y;
            asm volatile("red.global.add.v4.f32 [%0], {%1,%2,%3,%4};"
                :: "l"(phi + m * 16), "f"(e2), "f"(e3), "f"(o2), "f"(o3) : "memory");
        }
        __syncwarp();
    }
}

// ============================================================
// k_upd_mma: reads agg with inverse permutation; re-zeroes agg
// ============================================================
#define UB1H 0
#define UB1L 17408
#define UB2H 34816
#define UB2L 44032
#define UBIAS 53248
#define UA 53760
#define UPD_SMEM (53760 + 8 * 4352)

__global__ void __launch_bounds__(256, 2) k_upd_mma(
        const float* __restrict__ W1, const float* __restrict__ b1,
        const float* __restrict__ W2, const float* __restrict__ b2,
        int si, int di) {
    extern __shared__ char sm[];
    const uint32_t smb = smem_u32(sm);
    int tid = threadIdx.x, lane = tid & 31, wid = tid >> 5;

    for (int i = tid; i < 128 * 64; i += blockDim.x) {
        int k = i >> 6, n = i & 63;
        __half h, l; h_split(W1[i], h, l);
        ((__half*)(sm + UB1H))[n * 136 + k] = h;
        ((__half*)(sm + UB1L))[n * 136 + k] = l;
    }
    for (int i = tid; i < 64 * 64; i += blockDim.x) {
        int k = i >> 6, n = i & 63;
        __half h, l; h_split(W2[i], h, l);
        ((__half*)(sm + UB2H))[n * 72 + k] = h;
        ((__half*)(sm + UB2L))[n * 72 + k] = l;
    }
    if (tid < 64) {
        ((float*)(sm + UBIAS))[tid] = b1[tid];
        ((float*)(sm + UBIAS + 256))[tid] = b2[tid];
    }
    __syncthreads();

    const float* b1s = (const float*)(sm + UBIAS);
    const float* b2s = (const float*)(sm + UBIAS + 256);
    float* xd = g_xb[di];

    const int tig = lane & 3, gid = lane >> 2;
    const int wagg = (2 * (lane >> 3) + (lane & 1)) * 4 + ((lane >> 1) & 3);
    const uint32_t aRow = smb + UA + wid * 4352 + (lane & 15) * 272 + (lane & 16);
    const uint32_t bRow  = ((lane & 7) + ((lane & 16) >> 1));
    const uint32_t b1AddrH = smb + UB1H + bRow * 272 + (lane & 8) * 2;
    const uint32_t b1AddrL = b1AddrH + (UB1L - UB1H);
    const uint32_t b2AddrH = smb + UB2H + bRow * 144 + (lane & 8) * 2;
    const uint32_t b2AddrL = b2AddrH + (UB2L - UB2H);
    char* aRowPtr = sm + UA + wid * 4352;

    int gw = blockIdx.x * 8 + wid;
    int nw = gridDim.x * 8;
    for (int chunk = gw; chunk < NN / 16; chunk += nw) {
        int base16 = chunk * 16;
        #pragma unroll 4
        for (int t = 0; t < 16; t++) {
            int n = base16 + t;
            float2* agp = (float2*)(g_agg + (size_t)n * H) + lane;
            float2 ag = *agp;
            *agp = make_float2(0.f, 0.f);
            char* rp = aRowPtr + t * 272;
            ((unsigned*)rp)[lane]         = g_xf[n * 32 + lane];
            ((unsigned*)(rp + 128))[wagg] = pack_h2(ag.x, ag.y);
        }
        __syncwarp();

        float acc[8][4];
        #pragma unroll
        for (int n = 0; n < 8; n++)
            #pragma unroll
            for (int j = 0; j < 4; j++) acc[n][j] = 0.f;

        #pragma unroll 2
        for (int kt = 0; kt < 8; kt++) {
            uint32_t ah[4];
            LDSM4(ah, aRow + kt * 32);
            #pragma unroll
            for (int ng = 0; ng < 4; ng++) {
                uint32_t bh[4], bl[4];
                LDSM4(bh, b1AddrH + ng * 16 * 272 + kt * 32);
                LDSM4(bl, b1AddrL + ng * 16 * 272 + kt * 32);
                MMA16816(acc[2 * ng],     ah, bh[0], bh[1]);
                MMA16816(acc[2 * ng],     ah, bl[0], bl[1]);
                MMA16816(acc[2 * ng + 1], ah, bh[2], bh[3]);
                MMA16816(acc[2 * ng + 1], ah, bl[2], bl[3]);
            }
        }

        float acc2[8][4];
        #pragma unroll
        for (int n = 0; n < 8; n++)
            #pragma unroll
            for (int j = 0; j < 4; j++) acc2[n][j] = 0.f;

        #pragma unroll
        for (int kt = 0; kt < 4; kt++) {
            uint32_t a2[4];
            #pragma unroll
            for (int j = 0; j < 2; j++) {
                int nt = kt * 2 + j;
                float2 bb = *(const float2*)(b1s + nt * 8 + 2 * tig);
                float v0 = fmaxf(acc[nt][0] + bb.x, 0.f);
                float v1 = fmaxf(acc[nt][1] + bb.y, 0.f);
                float v2 = fmaxf(acc[nt][2] + bb.x, 0.f);
                float v3 = fmaxf(acc[nt][3] + bb.y, 0.f);
                a2[2 * j]     = pack_h2(v0, v1);
                a2[2 * j + 1] = pack_h2(v2, v3);
            }
            #pragma unroll
            for (int ng = 0; ng < 4; ng++) {
                uint32_t bh[4], bl[4];
                LDSM4(bh, b2AddrH + ng * 16 * 144 + kt * 32);
                LDSM4(bl, b2AddrL + ng * 16 * 144 + kt * 32);
                MMA16816(acc2[2 * ng],     a2, bh[0], bh[1]);
                MMA16816(acc2[2 * ng],     a2, bl[0], bl[1]);
                MMA16816(acc2[2 * ng + 1], a2, bh[2], bh[3]);
                MMA16816(acc2[2 * ng + 1], a2, bl[2], bl[3]);
            }
        }

        int n0 = base16 + gid, n1 = base16 + gid + 8;
        #pragma unroll
        for (int nt = 0; nt < 8; nt++) {
            float2 bb = *(const float2*)(b2s + nt * 8 + 2 * tig);
            float f0 = acc2[nt][0] + bb.x, f1 = acc2[nt][1] + bb.y;
            float f2 = acc2[nt][2] + bb.x, f3 = acc2[nt][3] + bb.y;
            *(float2*)(xd + (size_t)n0 * H + nt * 8 + 2 * tig) = make_float2(f0, f1);
            *(float2*)(xd + (size_t)n1 * H + nt * 8 + 2 * tig) = make_float2(f2, f3);
            g_xf[n0 * 32 + nt * 4 + tig] = pack_h2(f0, f1);
            g_xf[n1 * 32 + nt * 4 + tig] = pack_h2(f2, f3);
        }
        __syncwarp();
    }
}

// ============================================================
// k_enc_edge_mma: writes e fp16 in MMA A-fragment order
// ============================================================
#define EBH 0
#define EBL 9216
#define EBIAS 18432
#define EA 18688
#define ENC_SMEM (18688 + 8 * 2304)

__global__ void __launch_bounds__(256) k_enc_edge_mma(const float* __restrict__ ef,
        const float* __restrict__ W, const float* __restrict__ b) {
    extern __shared__ char sm[];
    const uint32_t smb = smem_u32(sm);
    int tid = threadIdx.x, lane = tid & 31, wid = tid >> 5;

    for (int i = tid; i < 64 * 64; i += blockDim.x) {
        int k = i >> 6, n = i & 63;
        __half h, l; h_split(W[i], h, l);
        ((__half*)(sm + EBH))[n * 72 + k] = h;
        ((__half*)(sm + EBL))[n * 72 + k] = l;
    }
    if (tid < 64) ((float*)(sm + EBIAS))[tid] = b[tid];
    __syncthreads();

    const float* bs = (const float*)(sm + EBIAS);
    const int tig = lane & 3;
    const int gi = lane >> 2;
    const uint32_t aRow = smb + EA + wid * 2304 + (lane & 15) * 144 + (lane & 16);
    const uint32_t bRow  = ((lane & 7) + ((lane & 16) >> 1));
    const uint32_t bAddrH = smb + EBH + bRow * 144 + (lane & 8) * 2;
    const uint32_t bAddrL = bAddrH + (EBL - EBH);
    char* aRowPtr = sm + EA + wid * 2304;

    int gw = blockIdx.x * 8 + wid;
    int nw = gridDim.x * 8;
    for (int chunk = gw; chunk < NE / 16; chunk += nw) {
        int base16 = chunk * 16;
        #pragma unroll 4
        for (int t = 0; t < 16; t++) {
            float2 v = ((const float2*)(ef + (size_t)(base16 + t) * H))[lane];
            ((unsigned*)(aRowPtr + t * 144))[lane] = pack_h2(v.x, v.y);
        }
        __syncwarp();

        float acc[8][4];
        #pragma unroll
        for (int n = 0; n < 8; n++)
            #pragma unroll
            for (int j = 0; j < 4; j++) acc[n][j] = 0.f;

        #pragma unroll
        for (int kt = 0; kt < 4; kt++) {
            uint32_t ah[4];
            LDSM4(ah, aRow + kt * 32);
            #pragma unroll
            for (int ng = 0; ng < 4; ng++) {
                uint32_t bh[4], bl[4];
                LDSM4(bh, bAddrH + ng * 16 * 144 + kt * 32);
                LDSM4(bl, bAddrL + ng * 16 * 144 + kt * 32);
                MMA16816(acc[2 * ng],     ah, bh[0], bh[1]);
                MMA16816(acc[2 * ng],     ah, bl[0], bl[1]);
                MMA16816(acc[2 * ng + 1], ah, bh[2], bh[3]);
                MMA16816(acc[2 * ng + 1], ah, bl[2], bl[3]);
            }
        }

        unsigned* de = g_et + (size_t)chunk * 512;
        #pragma unroll
        for (int nt = 0; nt < 8; nt++) {
            float2 bb = *(const float2*)(bs + nt * 8 + 2 * tig);
            float f0 = acc[nt][0] + bb.x, f1 = acc[nt][1] + bb.y;
            float f2 = acc[nt][2] + bb.x, f3 = acc[nt][3] + bb.y;
            int idx = (nt >> 1) * 128 + (gi * 4 + tig) * 4 + 2 * (nt & 1);
            de[idx]     = pack_h2(f0, f1);   // row gi
            de[idx + 1] = pack_h2(f2, f3);   // row gi+8
        }
        __syncwarp();
    }
}

// ============================================================
// k_enc_node: scalar f32x2; writes fp32 x + fp16 x
// ============================================================
__device__ __forceinline__ void ffma2(ull& d, ull a, ull b) {
    asm("fma.rn.f32x2 %0, %1, %2, %0;" : "+l"(d) : "l"(a), "l"(b));
}
__device__ __forceinline__ float fin(ull a, float b) {
    return __uint_as_float((unsigned)a) + __uint_as_float((unsigned)(a >> 32)) + b;
}

__global__ void __launch_bounds__(256) k_enc_node(const float* __restrict__ nf,
        const float* __restrict__ W, const float* __restrict__ b) {
    extern __shared__ float smf[];
    float* Wp   = smf;
    float* winb = Wp + 8320;
    int tid = threadIdx.x;
    for (int i = tid; i < 128 * 64; i += 256) {
        int k = i >> 6, c = i & 63;
        Wp[(c >> 1) * 260 + (k >> 1) * 4 + ((c & 1) << 1) + (k & 1)] = W[i];
    }
    __syncthreads();
    int lane = tid & 31, wid = tid >> 5;
    float2 bb = ((const float2*)b)[lane];
    float* win = winb + wid * 8 * ND;
    const ulonglong2* wl = (const ulonglong2*)(Wp + (size_t)lane * 260);
    int gw = blockIdx.x * 8 + wid;
    int nw = gridDim.x * 8;
    for (int base = gw * 8; base < NN; base += nw * 8) {
        #pragma unroll
        for (int t = 0; t < 8; t++) {
            float4 v = *(const float4*)(nf + (size_t)(base + t) * ND + lane * 4);
            *(float4*)(win + t * ND + lane * 4) = v;
        }
        __syncwarp();
        ull a0[8], a1[8];
        #pragma unroll
        for (int t = 0; t < 8; t++) { a0[t] = 0ull; a1[t] = 0ull; }
        #pragma unroll 4
        for (int c = 0; c < 32; c++) {
            ulonglong2 wA = wl[2 * c];
            ulonglong2 wB = wl[2 * c + 1];
            #pragma unroll
            for (int t = 0; t < 8; t++) {
                ulonglong2 v = ((const ulonglong2*)(win + t * ND))[c];
                ffma2(a0[t], wA.x, v.x); ffma2(a1[t], wA.y, v.x);
                ffma2(a0[t], wB.x, v.y); ffma2(a1[t], wB.y, v.y);
            }
        }
        #pragma unroll
        for (int t = 0; t < 8; t++) {
            float o0 = fin(a0[t], bb.x);
            float o1 = fin(a1[t], bb.y);
            int n = base + t;
            *(float2*)(g_xb[0] + (size_t)n * H + 2 * lane) = make_float2(o0, o1);
            g_xf[n * 32 + lane] = pack_h2(o0, o1);
        }
        __syncwarp();
    }
}

__global__ void k_con(const float* __restrict__ W1, const float* __restrict__ b1,
                      const float* __restrict__ w2, const float* __restrict__ b2,
                      int si, float* __restrict__ out) {
    __shared__ float Ws[H * H];
    __shared__ float bs[H];
    __shared__ float w2s[H];
    __shared__ float xb[8][H];
    __shared__ float b2v;
    int tid = threadIdx.x;
    for (int i = tid; i < H * H; i += blockDim.x) Ws[i] = W1[i];
    if (tid < H) { bs[tid] = b1[tid]; w2s[tid] = w2[tid]; }
    if (tid == 0) b2v = b2[0];
    __syncthreads();
    const float* xs = g_xb[si];
    int lane = tid & 31, wid = tid >> 5;
    int gw = blockIdx.x * 8 + wid;
    int nw = gridDim.x * 8;
    for (int n = gw; n < NN; n += nw) {
        float xv0 = xs[(size_t)n * H + lane];
        float xv1 = xs[(size_t)n * H + lane + 32];
        out[(size_t)n * H + lane]      = xv0;
        out[(size_t)n * H + lane + 32] = xv1;
        xb[wid][lane]      = xv0;
        xb[wid][lane + 32] = xv1;
        __syncwarp();
        float a0 = bs[lane], a1 = bs[lane + 32];
        #pragma unroll 4
        for (int k = 0; k < H; k++) {
            float v = xb[wid][k];
            a0 += v * Ws[k * H + lane];
            a1 += v * Ws[k * H + lane + 32];
        }
        float p = fmaxf(a0, 0.f) * w2s[lane] + fmaxf(a1, 0.f) * w2s[lane + 32];
        #pragma unroll
        for (int o = 16; o; o >>= 1) p += __shfl_xor_sync(0xffffffffu, p, o);
        if (lane == 0)
            out[(size_t)NN * H + n] = 1.f / (1.f + expf(-(p + b2v)));
        __syncwarp();
    }
}

extern "C" void kernel_launch(void* const* d_in, const int* in_sizes, int n_in,
                              void* d_out, int out_size) {
    const float* nf  = (const float*)d_in[0];
    const float* ef  = (const float*)d_in[1];
    const int*   ei  = (const int*)d_in[2];
    const float* enW = (const float*)d_in[3];
    const float* enb = (const float*)d_in[4];
    const float* eeW = (const float*)d_in[5];
    const float* eeb = (const float*)d_in[6];
    const float* mW1 = (const float*)d_in[7];
    const float* mb1 = (const float*)d_in[8];
    const float* mW2 = (const float*)d_in[9];
    const float* mb2 = (const float*)d_in[10];
    const float* uW1 = (const float*)d_in[11];
    const float* ub1 = (const float*)d_in[12];
    const float* uW2 = (const float*)d_in[13];
    const float* ub2 = (const float*)d_in[14];
    const float* cW1 = (const float*)d_in[15];
    const float* cb1 = (const float*)d_in[16];
    const float* cW2 = (const float*)d_in[17];
    const float* cb2 = (const float*)d_in[18];
    float* out = (float*)d_out;

    int dev = 0, smc = 148;
    cudaGetDevice(&dev);
    cudaDeviceGetAttribute(&smc, cudaDevAttrMultiProcessorCount, dev);

    const int ENN_SMEM = (8320 + 8192) * 4;
    cudaFuncSetAttribute(k_pre,          cudaFuncAttributeMaxDynamicSharedMemorySize, PRE_SMEM);
    cudaFuncSetAttribute(k_msg_mma,      cudaFuncAttributeMaxDynamicSharedMemorySize, MSG_SMEM);
    cudaFuncSetAttribute(k_upd_mma,      cudaFuncAttributeMaxDynamicSharedMemorySize, UPD_SMEM);
    cudaFuncSetAttribute(k_enc_edge_mma, cudaFuncAttributeMaxDynamicSharedMemorySize, ENC_SMEM);
    cudaFuncSetAttribute(k_enc_node,     cudaFuncAttributeMaxDynamicSharedMemorySize, ENN_SMEM);

    k_enc_node<<<smc * 2, 256, ENN_SMEM>>>(nf, enW, enb);
    k_enc_edge_mma<<<smc * 2, 256, ENC_SMEM>>>(ef, eeW, eeb);

    int cur = 0;
    for (int l = 0; l < 3; l++) {
        k_pre<<<smc * 2, 256, PRE_SMEM>>>(mW1 + (size_t)l * 192 * H, mb1 + l * H);
        k_msg_mma<<<smc * 2, 256, MSG_SMEM>>>(ei,
                                              mW1 + (size_t)l * 192 * H,
                                              mW2 + (size_t)l * H * H, mb2 + l * H);
        k_upd_mma<<<smc * 2, 256, UPD_SMEM>>>(uW1 + (size_t)l * 128 * H, ub1 + l * H,
                                              uW2 + (size_t)l * H * H,   ub2 + l * H,
                                              cur, 1 - cur);
        cur = 1 - cur;
    }
    k_con<<<1184, 256>>>(cW1, cb1, cW2, cb2, cur, out);
}

// round 14
// speedup vs baseline: 1.3914x; 1.2300x over previous
#include <cuda_runtime.h>
#include <cuda_fp16.h>
#include <math.h>
#include <cstdint>

#define NN 50000
#define NE 800000
#define H  64
#define ND 128

__device__ float g_xb[2][NN * H];
__device__ float g_agg[NN * H];              // PERMUTED cols
__device__ unsigned g_psh[NN * 32];          // Ps fp16 packed, word = tig*8 + nt
__device__ unsigned g_pdh[NN * 32];          // Pd fp16 packed
__device__ unsigned g_et[(size_t)NE * 32];   // e fp16 in MMA A-fragment order per 16-edge chunk
__device__ unsigned g_xf[NN * 32];           // x fp16 (2 cols/word)

typedef unsigned long long ull;

__device__ __forceinline__ uint32_t smem_u32(const void* p) {
    uint32_t a;
    asm("{ .reg .u64 t; cvta.to.shared.u64 t, %1; cvt.u32.u64 %0, t; }" : "=r"(a) : "l"(p));
    return a;
}

#define LDSM4(r, addr) \
    asm volatile("ldmatrix.sync.aligned.m8n8.x4.shared.b16 {%0,%1,%2,%3}, [%4];" \
        : "=r"((r)[0]), "=r"((r)[1]), "=r"((r)[2]), "=r"((r)[3]) : "r"(addr))

#define MMA16816(c, a, b0v, b1v) \
    asm volatile("mma.sync.aligned.m16n8k16.row.col.f32.f16.f16.f32 " \
        "{%0,%1,%2,%3},{%4,%5,%6,%7},{%8,%9},{%0,%1,%2,%3};" \
        : "+f"((c)[0]), "+f"((c)[1]), "+f"((c)[2]), "+f"((c)[3]) \
        : "r"((a)[0]), "r"((a)[1]), "r"((a)[2]), "r"((a)[3]), "r"(b0v), "r"(b1v))

__device__ __forceinline__ void h_split(float v, __half& h, __half& l) {
    h = __float2half_rn(v);
    l = __float2half_rn(v - __half2float(h));
}
__device__ __forceinline__ unsigned pack_h2(float a, float b) {
    __half2 t = __floats2half2_rn(a, b);
    return *reinterpret_cast<unsigned*>(&t);
}
__device__ __forceinline__ float2 h2f(unsigned u) {
    return __half22float2(*reinterpret_cast<__half2*>(&u));
}

// ============================================================
// k_pre: Ps = x@W1s + b1, Pd = x@W1d  (fp16 packed); zeroes g_agg
// ============================================================
#define PBSH 0
#define PBSL 9216
#define PBDH 18432
#define PBDL 27648
#define PBIAS 36864
#define PA 37120
#define PRE_SMEM (37120 + 8 * 2304)

__global__ void __launch_bounds__(256) k_pre(const float* __restrict__ W1,
                                             const float* __restrict__ b1) {
    extern __shared__ char sm[];
    const uint32_t smb = smem_u32(sm);
    int tid = threadIdx.x, lane = tid & 31, wid = tid >> 5;

    for (int i = tid; i < 64 * 64; i += blockDim.x) {
        int k = i >> 6, n = i & 63;
        __half h, l;
        h_split(W1[k * 64 + n], h, l);
        ((__half*)(sm + PBSH))[n * 72 + k] = h;
        ((__half*)(sm + PBSL))[n * 72 + k] = l;
        h_split(W1[(128 + k) * 64 + n], h, l);
        ((__half*)(sm + PBDH))[n * 72 + k] = h;
        ((__half*)(sm + PBDL))[n * 72 + k] = l;
    }
    if (tid < 64) ((float*)(sm + PBIAS))[tid] = b1[tid];
    __syncthreads();

    const float* b1s = (const float*)(sm + PBIAS);
    const int tig = lane & 3, gid = lane >> 2;
    const uint32_t aRow = smb + PA + wid * 2304 + (lane & 15) * 144 + (lane & 16);
    const uint32_t bRow  = ((lane & 7) + ((lane & 16) >> 1));
    const uint32_t bsH = smb + PBSH + bRow * 144 + (lane & 8) * 2;
    const uint32_t bsL = bsH + (PBSL - PBSH);
    const uint32_t bdH = smb + PBDH + bRow * 144 + (lane & 8) * 2;
    const uint32_t bdL = bdH + (PBDL - PBDH);
    char* aRowPtr = sm + PA + wid * 2304;

    int gw = blockIdx.x * 8 + wid;
    int nw = gridDim.x * 8;
    for (int chunk = gw; chunk < NN / 16; chunk += nw) {
        int base16 = chunk * 16;
        #pragma unroll 4
        for (int t = 0; t < 16; t++)
            ((unsigned*)(aRowPtr + t * 144))[lane] = g_xf[(base16 + t) * 32 + lane];
        __syncwarp();

        float as[8][4], ad[8][4];
        #pragma unroll
        for (int n = 0; n < 8; n++)
            #pragma unroll
            for (int j = 0; j < 4; j++) { as[n][j] = 0.f; ad[n][j] = 0.f; }

        #pragma unroll
        for (int kt = 0; kt < 4; kt++) {
            uint32_t ah[4];
            LDSM4(ah, aRow + kt * 32);
            #pragma unroll
            for (int ng = 0; ng < 4; ng++) {
                uint32_t bh[4], bl[4];
                LDSM4(bh, bsH + ng * 16 * 144 + kt * 32);
                LDSM4(bl, bsL + ng * 16 * 144 + kt * 32);
                MMA16816(as[2 * ng],     ah, bh[0], bh[1]);
                MMA16816(as[2 * ng],     ah, bl[0], bl[1]);
                MMA16816(as[2 * ng + 1], ah, bh[2], bh[3]);
                MMA16816(as[2 * ng + 1], ah, bl[2], bl[3]);
                LDSM4(bh, bdH + ng * 16 * 144 + kt * 32);
                LDSM4(bl, bdL + ng * 16 * 144 + kt * 32);
                MMA16816(ad[2 * ng],     ah, bh[0], bh[1]);
                MMA16816(ad[2 * ng],     ah, bl[0], bl[1]);
                MMA16816(ad[2 * ng + 1], ah, bh[2], bh[3]);
                MMA16816(ad[2 * ng + 1], ah, bl[2], bl[3]);
            }
        }

        int n0 = base16 + gid, n1 = base16 + gid + 8;
        unsigned ps0[8], ps1[8], pd0[8], pd1[8];
        #pragma unroll
        for (int nt = 0; nt < 8; nt++) {
            float2 bb = *(const float2*)(b1s + nt * 8 + 2 * tig);
            int c = nt * 8 + 2 * tig;
            ps0[nt] = pack_h2(as[nt][0] + bb.x, as[nt][1] + bb.y);
            ps1[nt] = pack_h2(as[nt][2] + bb.x, as[nt][3] + bb.y);
            pd0[nt] = pack_h2(ad[nt][0], ad[nt][1]);
            pd1[nt] = pack_h2(ad[nt][2], ad[nt][3]);
            *(float2*)(g_agg + (size_t)n0 * H + c) = make_float2(0.f, 0.f);
            *(float2*)(g_agg + (size_t)n1 * H + c) = make_float2(0.f, 0.f);
        }
        *(uint4*)(g_psh + n0 * 32 + tig * 8)     = make_uint4(ps0[0], ps0[1], ps0[2], ps0[3]);
        *(uint4*)(g_psh + n0 * 32 + tig * 8 + 4) = make_uint4(ps0[4], ps0[5], ps0[6], ps0[7]);
        *(uint4*)(g_psh + n1 * 32 + tig * 8)     = make_uint4(ps1[0], ps1[1], ps1[2], ps1[3]);
        *(uint4*)(g_psh + n1 * 32 + tig * 8 + 4) = make_uint4(ps1[4], ps1[5], ps1[6], ps1[7]);
        *(uint4*)(g_pdh + n0 * 32 + tig * 8)     = make_uint4(pd0[0], pd0[1], pd0[2], pd0[3]);
        *(uint4*)(g_pdh + n0 * 32 + tig * 8 + 4) = make_uint4(pd0[4], pd0[5], pd0[6], pd0[7]);
        *(uint4*)(g_pdh + n1 * 32 + tig * 8)     = make_uint4(pd1[0], pd1[1], pd1[2], pd1[3]);
        *(uint4*)(g_pdh + n1 * 32 + tig * 8 + 4) = make_uint4(pd1[4], pd1[5], pd1[6], pd1[7]);
        __syncwarp();
    }
}

// ============================================================
// k_msg_mma: A from global (fragment order), hi-only weights,
//            fp16 Ps/Pd gathers (explicit unpack)
// ============================================================
#define MB1H 0
#define MB2H 9216
#define MBIAS 18432
#define MSG_SMEM 18944

__global__ void __launch_bounds__(256, 2) k_msg_mma(const int* __restrict__ ei,
        const float* __restrict__ W1, const float* __restrict__ W2,
        const float* __restrict__ b2) {
    extern __shared__ char sm[];
    const uint32_t smb = smem_u32(sm);
    int tid = threadIdx.x, lane = tid & 31, wid = tid >> 5;

    for (int i = tid; i < 64 * 64; i += blockDim.x) {
        int k = i >> 6, n = i & 63;
        ((__half*)(sm + MB1H))[n * 72 + k] = __float2half_rn(W1[(64 + k) * 64 + n]);
        ((__half*)(sm + MB2H))[n * 72 + k] = __float2half_rn(W2[k * 64 + n]);
    }
    if (tid < 64) ((float*)(sm + MBIAS))[tid] = b2[tid];
    __syncthreads();

    const float* b2s = (const float*)(sm + MBIAS);
    const int tig = lane & 3, gid = lane >> 2;
    const uint32_t bRow  = ((lane & 7) + ((lane & 16) >> 1));
    const uint32_t b1H = smb + MB1H + bRow * 144 + (lane & 8) * 2;
    const uint32_t b2H = smb + MB2H + bRow * 144 + (lane & 8) * 2;

    const uint4* et4 = (const uint4*)g_et;
    const int NCH = NE / 16;
    int gw = blockIdx.x * 8 + wid;
    int nw = gridDim.x * 8;

    for (int chunk = gw; chunk < NCH; chunk += nw) {
        int base16 = chunk * 16;
        int s = 0, d = 0;
        if (lane < 16) { s = ei[base16 + lane]; d = ei[NE + base16 + lane]; }
        int s0 = __shfl_sync(0xffffffffu, s, gid), s1 = __shfl_sync(0xffffffffu, s, gid + 8);
        int d0 = __shfl_sync(0xffffffffu, d, gid), d1 = __shfl_sync(0xffffffffu, d, gid + 8);

        // A fragments straight from global (4 x LDG.128)
        uint4 A[4];
        #pragma unroll
        for (int kt = 0; kt < 4; kt++)
            A[kt] = __ldg(et4 + (size_t)chunk * 128 + kt * 32 + lane);

        // layer 1 (e-term): K=64, hi-only weights
        float acc[8][4];
        #pragma unroll
        for (int n = 0; n < 8; n++)
            #pragma unroll
            for (int j = 0; j < 4; j++) acc[n][j] = 0.f;

        #pragma unroll
        for (int kt = 0; kt < 4; kt++) {
            uint32_t ah[4] = {A[kt].x, A[kt].y, A[kt].z, A[kt].w};
            #pragma unroll
            for (int ng = 0; ng < 4; ng++) {
                uint32_t bh[4];
                LDSM4(bh, b1H + ng * 16 * 144 + kt * 32);
                MMA16816(acc[2 * ng],     ah, bh[0], bh[1]);
                MMA16816(acc[2 * ng + 1], ah, bh[2], bh[3]);
            }
        }

        // Ps/Pd gathers: fp16 packed, 32B per node -> 2 x LDG.128 each
        unsigned P0w[8], P1w[8], Q0w[8], Q1w[8];
        {
            const uint4* p0 = (const uint4*)(g_psh + s0 * 32 + tig * 8);
            const uint4* p1 = (const uint4*)(g_psh + s1 * 32 + tig * 8);
            const uint4* q0 = (const uint4*)(g_pdh + d0 * 32 + tig * 8);
            const uint4* q1 = (const uint4*)(g_pdh + d1 * 32 + tig * 8);
            uint4 a, b;
            a = __ldg(p0); b = __ldg(p0 + 1);
            P0w[0]=a.x; P0w[1]=a.y; P0w[2]=a.z; P0w[3]=a.w;
            P0w[4]=b.x; P0w[5]=b.y; P0w[6]=b.z; P0w[7]=b.w;
            a = __ldg(p1); b = __ldg(p1 + 1);
            P1w[0]=a.x; P1w[1]=a.y; P1w[2]=a.z; P1w[3]=a.w;
            P1w[4]=b.x; P1w[5]=b.y; P1w[6]=b.z; P1w[7]=b.w;
            a = __ldg(q0); b = __ldg(q0 + 1);
            Q0w[0]=a.x; Q0w[1]=a.y; Q0w[2]=a.z; Q0w[3]=a.w;
            Q0w[4]=b.x; Q0w[5]=b.y; Q0w[6]=b.z; Q0w[7]=b.w;
            a = __ldg(q1); b = __ldg(q1 + 1);
            Q1w[0]=a.x; Q1w[1]=a.y; Q1w[2]=a.z; Q1w[3]=a.w;
            Q1w[4]=b.x; Q1w[5]=b.y; Q1w[6]=b.z; Q1w[7]=b.w;
        }

        // layer 2 fused per kt, hi-only weights
        float acc2[8][4];
        #pragma unroll
        for (int n = 0; n < 8; n++)
            #pragma unroll
            for (int j = 0; j < 4; j++) acc2[n][j] = 0.f;

        #pragma unroll
        for (int kt = 0; kt < 4; kt++) {
            uint32_t a2[4];
            #pragma unroll
            for (int j = 0; j < 2; j++) {
                int nt = 2 * kt + j;
                float2 p0v = h2f(P0w[nt]), q0v = h2f(Q0w[nt]);
                float2 p1v = h2f(P1w[nt]), q1v = h2f(Q1w[nt]);
                float v0 = fmaxf(acc[nt][0] + p0v.x + q0v.x, 0.f);
                float v1 = fmaxf(acc[nt][1] + p0v.y + q0v.y, 0.f);
                float v2 = fmaxf(acc[nt][2] + p1v.x + q1v.x, 0.f);
                float v3 = fmaxf(acc[nt][3] + p1v.y + q1v.y, 0.f);
                a2[2 * j]     = pack_h2(v0, v1);
                a2[2 * j + 1] = pack_h2(v2, v3);
            }
            #pragma unroll
            for (int ng = 0; ng < 4; ng++) {
                uint32_t bh[4];
                LDSM4(bh, b2H + ng * 16 * 144 + kt * 32);
                MMA16816(acc2[2 * ng],     a2, bh[0], bh[1]);
                MMA16816(acc2[2 * ng + 1], a2, bh[2], bh[3]);
            }
        }

        // epilogue: permuted agg cols -> red.v4
        float* plo = g_agg + (size_t)d0 * H + tig * 4;
        float* phi = g_agg + (size_t)d1 * H + tig * 4;
        #pragma unroll
        for (int m = 0; m < 4; m++) {
            float2 be = *(const float2*)(b2s + (2 * m) * 8 + 2 * tig);
            float2 bo = *(const float2*)(b2s + (2 * m + 1) * 8 + 2 * tig);
            float e0 = acc2[2 * m][0] + be.x, e1 = acc2[2 * m][1] + be.y;
            float o0 = acc2[2 * m + 1][0] + bo.x, o1 = acc2[2 * m + 1][1] + bo.y;
            asm volatile("red.global.add.v4.f32 [%0], {%1,%2,%3,%4};"
                :: "l"(plo + m * 16), "f"(e0), "f"(e1), "f"(o0), "f"(o1) : "memory");
            float e2 = acc2[2 * m][2] + be.x, e3 = acc2[2 * m][3] + be.y;
            float o2 = acc2[2 * m + 1][2] + bo.x, o3 = acc2[2 * m + 1][3] + bo.y;
            asm volatile("red.global.add.v4.f32 [%0], {%1,%2,%3,%4};"
                :: "l"(phi + m * 16), "f"(e2), "f"(e3), "f"(o2), "f"(o3) : "memory");
        }
        __syncwarp();
    }
}

// ============================================================
// k_upd_mma: reads agg with inverse permutation; re-zeroes agg
// ============================================================
#define UB1H 0
#define UB1L 17408
#define UB2H 34816
#define UB2L 44032
#define UBIAS 53248
#define UA 53760
#define UPD_SMEM (53760 + 8 * 4352)

__global__ void __launch_bounds__(256, 2) k_upd_mma(
        const float* __restrict__ W1, const float* __restrict__ b1,
        const float* __restrict__ W2, const float* __restrict__ b2,
        int si, int di) {
    extern __shared__ char sm[];
    const uint32_t smb = smem_u32(sm);
    int tid = threadIdx.x, lane = tid & 31, wid = tid >> 5;

    for (int i = tid; i < 128 * 64; i += blockDim.x) {
        int k = i >> 6, n = i & 63;
        __half h, l; h_split(W1[i], h, l);
        ((__half*)(sm + UB1H))[n * 136 + k] = h;
        ((__half*)(sm + UB1L))[n * 136 + k] = l;
    }
    for (int i = tid; i < 64 * 64; i += blockDim.x) {
        int k = i >> 6, n = i & 63;
        __half h, l; h_split(W2[i], h, l);
        ((__half*)(sm + UB2H))[n * 72 + k] = h;
        ((__half*)(sm + UB2L))[n * 72 + k] = l;
    }
    if (tid < 64) {
        ((float*)(sm + UBIAS))[tid] = b1[tid];
        ((float*)(sm + UBIAS + 256))[tid] = b2[tid];
    }
    __syncthreads();

    const float* b1s = (const float*)(sm + UBIAS);
    const float* b2s = (const float*)(sm + UBIAS + 256);
    float* xd = g_xb[di];

    const int tig = lane & 3, gid = lane >> 2;
    const int wagg = (2 * (lane >> 3) + (lane & 1)) * 4 + ((lane >> 1) & 3);
    const uint32_t aRow = smb + UA + wid * 4352 + (lane & 15) * 272 + (lane & 16);
    const uint32_t bRow  = ((lane & 7) + ((lane & 16) >> 1));
    const uint32_t b1AddrH = smb + UB1H + bRow * 272 + (lane & 8) * 2;
    const uint32_t b1AddrL = b1AddrH + (UB1L - UB1H);
    const uint32_t b2AddrH = smb + UB2H + bRow * 144 + (lane & 8) * 2;
    const uint32_t b2AddrL = b2AddrH + (UB2L - UB2H);
    char* aRowPtr = sm + UA + wid * 4352;

    int gw = blockIdx.x * 8 + wid;
    int nw = gridDim.x * 8;
    for (int chunk = gw; chunk < NN / 16; chunk += nw) {
        int base16 = chunk * 16;
        #pragma unroll 4
        for (int t = 0; t < 16; t++) {
            int n = base16 + t;
            float2* agp = (float2*)(g_agg + (size_t)n * H) + lane;
            float2 ag = *agp;
            *agp = make_float2(0.f, 0.f);
            char* rp = aRowPtr + t * 272;
            ((unsigned*)rp)[lane]         = g_xf[n * 32 + lane];
            ((unsigned*)(rp + 128))[wagg] = pack_h2(ag.x, ag.y);
        }
        __syncwarp();

        float acc[8][4];
        #pragma unroll
        for (int n = 0; n < 8; n++)
            #pragma unroll
            for (int j = 0; j < 4; j++) acc[n][j] = 0.f;

        #pragma unroll 2
        for (int kt = 0; kt < 8; kt++) {
            uint32_t ah[4];
            LDSM4(ah, aRow + kt * 32);
            #pragma unroll
            for (int ng = 0; ng < 4; ng++) {
                uint32_t bh[4], bl[4];
                LDSM4(bh, b1AddrH + ng * 16 * 272 + kt * 32);
                LDSM4(bl, b1AddrL + ng * 16 * 272 + kt * 32);
                MMA16816(acc[2 * ng],     ah, bh[0], bh[1]);
                MMA16816(acc[2 * ng],     ah, bl[0], bl[1]);
                MMA16816(acc[2 * ng + 1], ah, bh[2], bh[3]);
                MMA16816(acc[2 * ng + 1], ah, bl[2], bl[3]);
            }
        }

        float acc2[8][4];
        #pragma unroll
        for (int n = 0; n < 8; n++)
            #pragma unroll
            for (int j = 0; j < 4; j++) acc2[n][j] = 0.f;

        #pragma unroll
        for (int kt = 0; kt < 4; kt++) {
            uint32_t a2[4];
            #pragma unroll
            for (int j = 0; j < 2; j++) {
                int nt = kt * 2 + j;
                float2 bb = *(const float2*)(b1s + nt * 8 + 2 * tig);
                float v0 = fmaxf(acc[nt][0] + bb.x, 0.f);
                float v1 = fmaxf(acc[nt][1] + bb.y, 0.f);
                float v2 = fmaxf(acc[nt][2] + bb.x, 0.f);
                float v3 = fmaxf(acc[nt][3] + bb.y, 0.f);
                a2[2 * j]     = pack_h2(v0, v1);
                a2[2 * j + 1] = pack_h2(v2, v3);
            }
            #pragma unroll
            for (int ng = 0; ng < 4; ng++) {
                uint32_t bh[4], bl[4];
                LDSM4(bh, b2AddrH + ng * 16 * 144 + kt * 32);
                LDSM4(bl, b2AddrL + ng * 16 * 144 + kt * 32);
                MMA16816(acc2[2 * ng],     a2, bh[0], bh[1]);
                MMA16816(acc2[2 * ng],     a2, bl[0], bl[1]);
                MMA16816(acc2[2 * ng + 1], a2, bh[2], bh[3]);
                MMA16816(acc2[2 * ng + 1], a2, bl[2], bl[3]);
            }
        }

        int n0 = base16 + gid, n1 = base16 + gid + 8;
        #pragma unroll
        for (int nt = 0; nt < 8; nt++) {
            float2 bb = *(const float2*)(b2s + nt * 8 + 2 * tig);
            float f0 = acc2[nt][0] + bb.x, f1 = acc2[nt][1] + bb.y;
            float f2 = acc2[nt][2] + bb.x, f3 = acc2[nt][3] + bb.y;
            *(float2*)(xd + (size_t)n0 * H + nt * 8 + 2 * tig) = make_float2(f0, f1);
            *(float2*)(xd + (size_t)n1 * H + nt * 8 + 2 * tig) = make_float2(f2, f3);
            g_xf[n0 * 32 + nt * 4 + tig] = pack_h2(f0, f1);
            g_xf[n1 * 32 + nt * 4 + tig] = pack_h2(f2, f3);
        }
        __syncwarp();
    }
}

// ============================================================
// k_enc_edge_mma: writes e fp16 in MMA A-fragment order
// ============================================================
#define EBH 0
#define EBL 9216
#define EBIAS 18432
#define EA 18688
#define ENC_SMEM (18688 + 8 * 2304)

__global__ void __launch_bounds__(256) k_enc_edge_mma(const float* __restrict__ ef,
        const float* __restrict__ W, const float* __restrict__ b) {
    extern __shared__ char sm[];
    const uint32_t smb = smem_u32(sm);
    int tid = threadIdx.x, lane = tid & 31, wid = tid >> 5;

    for (int i = tid; i < 64 * 64; i += blockDim.x) {
        int k = i >> 6, n = i & 63;
        __half h, l; h_split(W[i], h, l);
        ((__half*)(sm + EBH))[n * 72 + k] = h;
        ((__half*)(sm + EBL))[n * 72 + k] = l;
    }
    if (tid < 64) ((float*)(sm + EBIAS))[tid] = b[tid];
    __syncthreads();

    const float* bs = (const float*)(sm + EBIAS);
    const int tig = lane & 3;
    const int gi = lane >> 2;
    const uint32_t aRow = smb + EA + wid * 2304 + (lane & 15) * 144 + (lane & 16);
    const uint32_t bRow  = ((lane & 7) + ((lane & 16) >> 1));
    const uint32_t bAddrH = smb + EBH + bRow * 144 + (lane & 8) * 2;
    const uint32_t bAddrL = bAddrH + (EBL - EBH);
    char* aRowPtr = sm + EA + wid * 2304;

    int gw = blockIdx.x * 8 + wid;
    int nw = gridDim.x * 8;
    for (int chunk = gw; chunk < NE / 16; chunk += nw) {
        int base16 = chunk * 16;
        #pragma unroll 4
        for (int t = 0; t < 16; t++) {
            float2 v = ((const float2*)(ef + (size_t)(base16 + t) * H))[lane];
            ((unsigned*)(aRowPtr + t * 144))[lane] = pack_h2(v.x, v.y);
        }
        __syncwarp();

        float acc[8][4];
        #pragma unroll
        for (int n = 0; n < 8; n++)
            #pragma unroll
            for (int j = 0; j < 4; j++) acc[n][j] = 0.f;

        #pragma unroll
        for (int kt = 0; kt < 4; kt++) {
            uint32_t ah[4];
            LDSM4(ah, aRow + kt * 32);
            #pragma unroll
            for (int ng = 0; ng < 4; ng++) {
                uint32_t bh[4], bl[4];
                LDSM4(bh, bAddrH + ng * 16 * 144 + kt * 32);
                LDSM4(bl, bAddrL + ng * 16 * 144 + kt * 32);
                MMA16816(acc[2 * ng],     ah, bh[0], bh[1]);
                MMA16816(acc[2 * ng],     ah, bl[0], bl[1]);
                MMA16816(acc[2 * ng + 1], ah, bh[2], bh[3]);
                MMA16816(acc[2 * ng + 1], ah, bl[2], bl[3]);
            }
        }

        unsigned* de = g_et + (size_t)chunk * 512;
        #pragma unroll
        for (int nt = 0; nt < 8; nt++) {
            float2 bb = *(const float2*)(bs + nt * 8 + 2 * tig);
            float f0 = acc[nt][0] + bb.x, f1 = acc[nt][1] + bb.y;
            float f2 = acc[nt][2] + bb.x, f3 = acc[nt][3] + bb.y;
            int idx = (nt >> 1) * 128 + (gi * 4 + tig) * 4 + 2 * (nt & 1);
            de[idx]     = pack_h2(f0, f1);
            de[idx + 1] = pack_h2(f2, f3);
        }
        __syncwarp();
    }
}

// ============================================================
// k_enc_node: scalar f32x2; writes fp32 x + fp16 x
// ============================================================
__device__ __forceinline__ void ffma2(ull& d, ull a, ull b) {
    asm("fma.rn.f32x2 %0, %1, %2, %0;" : "+l"(d) : "l"(a), "l"(b));
}
__device__ __forceinline__ float fin(ull a, float b) {
    return __uint_as_float((unsigned)a) + __uint_as_float((unsigned)(a >> 32)) + b;
}

__global__ void __launch_bounds__(256) k_enc_node(const float* __restrict__ nf,
        const float* __restrict__ W, const float* __restrict__ b) {
    extern __shared__ float smf[];
    float* Wp   = smf;
    float* winb = Wp + 8320;
    int tid = threadIdx.x;
    for (int i = tid; i < 128 * 64; i += 256) {
        int k = i >> 6, c = i & 63;
        Wp[(c >> 1) * 260 + (k >> 1) * 4 + ((c & 1) << 1) + (k & 1)] = W[i];
    }
    __syncthreads();
    int lane = tid & 31, wid = tid >> 5;
    float2 bb = ((const float2*)b)[lane];
    float* win = winb + wid * 8 * ND;
    const ulonglong2* wl = (const ulonglong2*)(Wp + (size_t)lane * 260);
    int gw = blockIdx.x * 8 + wid;
    int nw = gridDim.x * 8;
    for (int base = gw * 8; base < NN; base += nw * 8) {
        #pragma unroll
        for (int t = 0; t < 8; t++) {
            float4 v = *(const float4*)(nf + (size_t)(base + t) * ND + lane * 4);
            *(float4*)(win + t * ND + lane * 4) = v;
        }
        __syncwarp();
        ull a0[8], a1[8];
        #pragma unroll
        for (int t = 0; t < 8; t++) { a0[t] = 0ull; a1[t] = 0ull; }
        #pragma unroll 4
        for (int c = 0; c < 32; c++) {
            ulonglong2 wA = wl[2 * c];
            ulonglong2 wB = wl[2 * c + 1];
            #pragma unroll
            for (int t = 0; t < 8; t++) {
                ulonglong2 v = ((const ulonglong2*)(win + t * ND))[c];
                ffma2(a0[t], wA.x, v.x); ffma2(a1[t], wA.y, v.x);
                ffma2(a0[t], wB.x, v.y); ffma2(a1[t], wB.y, v.y);
            }
        }
        #pragma unroll
        for (int t = 0; t < 8; t++) {
            float o0 = fin(a0[t], bb.x);
            float o1 = fin(a1[t], bb.y);
            int n = base + t;
            *(float2*)(g_xb[0] + (size_t)n * H + 2 * lane) = make_float2(o0, o1);
            g_xf[n * 32 + lane] = pack_h2(o0, o1);
        }
        __syncwarp();
    }
}

__global__ void k_con(const float* __restrict__ W1, const float* __restrict__ b1,
                      const float* __restrict__ w2, const float* __restrict__ b2,
                      int si, float* __restrict__ out) {
    __shared__ float Ws[H * H];
    __shared__ float bs[H];
    __shared__ float w2s[H];
    __shared__ float xb[8][H];
    __shared__ float b2v;
    int tid = threadIdx.x;
    for (int i = tid; i < H * H; i += blockDim.x) Ws[i] = W1[i];
    if (tid < H) { bs[tid] = b1[tid]; w2s[tid] = w2[tid]; }
    if (tid == 0) b2v = b2[0];
    __syncthreads();
    const float* xs = g_xb[si];
    int lane = tid & 31, wid = tid >> 5;
    int gw = blockIdx.x * 8 + wid;
    int nw = gridDim.x * 8;
    for (int n = gw; n < NN; n += nw) {
        float xv0 = xs[(size_t)n * H + lane];
        float xv1 = xs[(size_t)n * H + lane + 32];
        out[(size_t)n * H + lane]      = xv0;
        out[(size_t)n * H + lane + 32] = xv1;
        xb[wid][lane]      = xv0;
        xb[wid][lane + 32] = xv1;
        __syncwarp();
        float a0 = bs[lane], a1 = bs[lane + 32];
        #pragma unroll 4
        for (int k = 0; k < H; k++) {
            float v = xb[wid][k];
            a0 += v * Ws[k * H + lane];
            a1 += v * Ws[k * H + lane + 32];
        }
        float p = fmaxf(a0, 0.f) * w2s[lane] + fmaxf(a1, 0.f) * w2s[lane + 32];
        #pragma unroll
        for (int o = 16; o; o >>= 1) p += __shfl_xor_sync(0xffffffffu, p, o);
        if (lane == 0)
            out[(size_t)NN * H + n] = 1.f / (1.f + expf(-(p + b2v)));
        __syncwarp();
    }
}

extern "C" void kernel_launch(void* const* d_in, const int* in_sizes, int n_in,
                              void* d_out, int out_size) {
    const float* nf  = (const float*)d_in[0];
    const float* ef  = (const float*)d_in[1];
    const int*   ei  = (const int*)d_in[2];
    const float* enW = (const float*)d_in[3];
    const float* enb = (const float*)d_in[4];
    const float* eeW = (const float*)d_in[5];
    const float* eeb = (const float*)d_in[6];
    const float* mW1 = (const float*)d_in[7];
    const float* mb1 = (const float*)d_in[8];
    const float* mW2 = (const float*)d_in[9];
    const float* mb2 = (const float*)d_in[10];
    const float* uW1 = (const float*)d_in[11];
    const float* ub1 = (const float*)d_in[12];
    const float* uW2 = (const float*)d_in[13];
    const float* ub2 = (const float*)d_in[14];
    const float* cW1 = (const float*)d_in[15];
    const float* cb1 = (const float*)d_in[16];
    const float* cW2 = (const float*)d_in[17];
    const float* cb2 = (const float*)d_in[18];
    float* out = (float*)d_out;

    int dev = 0, smc = 148;
    cudaGetDevice(&dev);
    cudaDeviceGetAttribute(&smc, cudaDevAttrMultiProcessorCount, dev);

    const int ENN_SMEM = (8320 + 8192) * 4;
    cudaFuncSetAttribute(k_pre,          cudaFuncAttributeMaxDynamicSharedMemorySize, PRE_SMEM);
    cudaFuncSetAttribute(k_msg_mma,      cudaFuncAttributeMaxDynamicSharedMemorySize, MSG_SMEM);
    cudaFuncSetAttribute(k_upd_mma,      cudaFuncAttributeMaxDynamicSharedMemorySize, UPD_SMEM);
    cudaFuncSetAttribute(k_enc_edge_mma, cudaFuncAttributeMaxDynamicSharedMemorySize, ENC_SMEM);
    cudaFuncSetAttribute(k_enc_node,     cudaFuncAttributeMaxDynamicSharedMemorySize, ENN_SMEM);

    k_enc_node<<<smc * 2, 256, ENN_SMEM>>>(nf, enW, enb);
    k_enc_edge_mma<<<smc * 2, 256, ENC_SMEM>>>(ef, eeW, eeb);

    int cur = 0;
    for (int l = 0; l < 3; l++) {
        k_pre<<<smc * 2, 256, PRE_SMEM>>>(mW1 + (size_t)l * 192 * H, mb1 + l * H);
        k_msg_mma<<<smc * 2, 256, MSG_SMEM>>>(ei,
                                              mW1 + (size_t)l * 192 * H,
                                              mW2 + (size_t)l * H * H, mb2 + l * H);
        k_upd_mma<<<smc * 2, 256, UPD_SMEM>>>(uW1 + (size_t)l * 128 * H, ub1 + l * H,
                                              uW2 + (size_t)l * H * H,   ub2 + l * H,
                                              cur, 1 - cur);
        cur = 1 - cur;
    }
    k_con<<<1184, 256>>>(cW1, cb1, cW2, cb2, cur, out);
}

// round 15
// speedup vs baseline: 1.4469x; 1.0398x over previous
#include <cuda_runtime.h>
#include <cuda_fp16.h>
#include <math.h>
#include <cstdint>

#define NN 50000
#define NE 800000
#define H  64
#define ND 128

__device__ float g_xb[2][NN * H];
__device__ float g_agg[NN * H];              // PERMUTED cols
__device__ unsigned g_psh[NN * 32];          // Ps fp16 packed, word = tig*8 + nt
__device__ unsigned g_pdh[NN * 32];          // Pd fp16 packed
__device__ unsigned g_et[(size_t)NE * 32];   // e fp16 in MMA A-fragment order
__device__ unsigned g_xf[NN * 32];           // x fp16 (2 cols/word)

typedef unsigned long long ull;

__device__ __forceinline__ uint32_t smem_u32(const void* p) {
    uint32_t a;
    asm("{ .reg .u64 t; cvta.to.shared.u64 t, %1; cvt.u32.u64 %0, t; }" : "=r"(a) : "l"(p));
    return a;
}

#define LDSM4(r, addr) \
    asm volatile("ldmatrix.sync.aligned.m8n8.x4.shared.b16 {%0,%1,%2,%3}, [%4];" \
        : "=r"((r)[0]), "=r"((r)[1]), "=r"((r)[2]), "=r"((r)[3]) : "r"(addr))

#define MMA16816(c, a, b0v, b1v) \
    asm volatile("mma.sync.aligned.m16n8k16.row.col.f32.f16.f16.f32 " \
        "{%0,%1,%2,%3},{%4,%5,%6,%7},{%8,%9},{%0,%1,%2,%3};" \
        : "+f"((c)[0]), "+f"((c)[1]), "+f"((c)[2]), "+f"((c)[3]) \
        : "r"((a)[0]), "r"((a)[1]), "r"((a)[2]), "r"((a)[3]), "r"(b0v), "r"(b1v))

__device__ __forceinline__ unsigned pack_h2(float a, float b) {
    __half2 t = __floats2half2_rn(a, b);
    return *reinterpret_cast<unsigned*>(&t);
}
__device__ __forceinline__ float2 h2f(unsigned u) {
    return __half22float2(*reinterpret_cast<__half2*>(&u));
}

// ============================================================
// k_pre: Ps = x@W1s + b1, Pd = x@W1d  (fp16 out, hi-only W)
// ============================================================
#define PBSH 0
#define PBDH 9216
#define PBIAS 18432
#define PA 18688
#define PRE_SMEM (18688 + 8 * 2304)

__global__ void __launch_bounds__(256) k_pre(const float* __restrict__ W1,
                                             const float* __restrict__ b1) {
    extern __shared__ char sm[];
    const uint32_t smb = smem_u32(sm);
    int tid = threadIdx.x, lane = tid & 31, wid = tid >> 5;

    for (int i = tid; i < 64 * 64; i += blockDim.x) {
        int k = i >> 6, n = i & 63;
        ((__half*)(sm + PBSH))[n * 72 + k] = __float2half_rn(W1[k * 64 + n]);
        ((__half*)(sm + PBDH))[n * 72 + k] = __float2half_rn(W1[(128 + k) * 64 + n]);
    }
    if (tid < 64) ((float*)(sm + PBIAS))[tid] = b1[tid];
    __syncthreads();

    const float* b1s = (const float*)(sm + PBIAS);
    const int tig = lane & 3, gid = lane >> 2;
    const uint32_t aRow = smb + PA + wid * 2304 + (lane & 15) * 144 + (lane & 16);
    const uint32_t bRow  = ((lane & 7) + ((lane & 16) >> 1));
    const uint32_t bsH = smb + PBSH + bRow * 144 + (lane & 8) * 2;
    const uint32_t bdH = smb + PBDH + bRow * 144 + (lane & 8) * 2;
    char* aRowPtr = sm + PA + wid * 2304;

    int gw = blockIdx.x * 8 + wid;
    int nw = gridDim.x * 8;
    for (int chunk = gw; chunk < NN / 16; chunk += nw) {
        int base16 = chunk * 16;
        #pragma unroll 4
        for (int t = 0; t < 16; t++)
            ((unsigned*)(aRowPtr + t * 144))[lane] = g_xf[(base16 + t) * 32 + lane];
        __syncwarp();

        float as[8][4], ad[8][4];
        #pragma unroll
        for (int n = 0; n < 8; n++)
            #pragma unroll
            for (int j = 0; j < 4; j++) { as[n][j] = 0.f; ad[n][j] = 0.f; }

        #pragma unroll
        for (int kt = 0; kt < 4; kt++) {
            uint32_t ah[4];
            LDSM4(ah, aRow + kt * 32);
            #pragma unroll
            for (int ng = 0; ng < 4; ng++) {
                uint32_t bh[4];
                LDSM4(bh, bsH + ng * 16 * 144 + kt * 32);
                MMA16816(as[2 * ng],     ah, bh[0], bh[1]);
                MMA16816(as[2 * ng + 1], ah, bh[2], bh[3]);
                LDSM4(bh, bdH + ng * 16 * 144 + kt * 32);
                MMA16816(ad[2 * ng],     ah, bh[0], bh[1]);
                MMA16816(ad[2 * ng + 1], ah, bh[2], bh[3]);
            }
        }

        int n0 = base16 + gid, n1 = base16 + gid + 8;
        unsigned ps0[8], ps1[8], pd0[8], pd1[8];
        #pragma unroll
        for (int nt = 0; nt < 8; nt++) {
            float2 bb = *(const float2*)(b1s + nt * 8 + 2 * tig);
            int c = nt * 8 + 2 * tig;
            ps0[nt] = pack_h2(as[nt][0] + bb.x, as[nt][1] + bb.y);
            ps1[nt] = pack_h2(as[nt][2] + bb.x, as[nt][3] + bb.y);
            pd0[nt] = pack_h2(ad[nt][0], ad[nt][1]);
            pd1[nt] = pack_h2(ad[nt][2], ad[nt][3]);
            *(float2*)(g_agg + (size_t)n0 * H + c) = make_float2(0.f, 0.f);
            *(float2*)(g_agg + (size_t)n1 * H + c) = make_float2(0.f, 0.f);
        }
        *(uint4*)(g_psh + n0 * 32 + tig * 8)     = make_uint4(ps0[0], ps0[1], ps0[2], ps0[3]);
        *(uint4*)(g_psh + n0 * 32 + tig * 8 + 4) = make_uint4(ps0[4], ps0[5], ps0[6], ps0[7]);
        *(uint4*)(g_psh + n1 * 32 + tig * 8)     = make_uint4(ps1[0], ps1[1], ps1[2], ps1[3]);
        *(uint4*)(g_psh + n1 * 32 + tig * 8 + 4) = make_uint4(ps1[4], ps1[5], ps1[6], ps1[7]);
        *(uint4*)(g_pdh + n0 * 32 + tig * 8)     = make_uint4(pd0[0], pd0[1], pd0[2], pd0[3]);
        *(uint4*)(g_pdh + n0 * 32 + tig * 8 + 4) = make_uint4(pd0[4], pd0[5], pd0[6], pd0[7]);
        *(uint4*)(g_pdh + n1 * 32 + tig * 8)     = make_uint4(pd1[0], pd1[1], pd1[2], pd1[3]);
        *(uint4*)(g_pdh + n1 * 32 + tig * 8 + 4) = make_uint4(pd1[4], pd1[5], pd1[6], pd1[7]);
        __syncwarp();
    }
}

// ============================================================
// k_msg_mma: unchanged from R14 (verified)
// ============================================================
#define MB1H 0
#define MB2H 9216
#define MBIAS 18432
#define MSG_SMEM 18944

__global__ void __launch_bounds__(256, 2) k_msg_mma(const int* __restrict__ ei,
        const float* __restrict__ W1, const float* __restrict__ W2,
        const float* __restrict__ b2) {
    extern __shared__ char sm[];
    const uint32_t smb = smem_u32(sm);
    int tid = threadIdx.x, lane = tid & 31, wid = tid >> 5;

    for (int i = tid; i < 64 * 64; i += blockDim.x) {
        int k = i >> 6, n = i & 63;
        ((__half*)(sm + MB1H))[n * 72 + k] = __float2half_rn(W1[(64 + k) * 64 + n]);
        ((__half*)(sm + MB2H))[n * 72 + k] = __float2half_rn(W2[k * 64 + n]);
    }
    if (tid < 64) ((float*)(sm + MBIAS))[tid] = b2[tid];
    __syncthreads();

    const float* b2s = (const float*)(sm + MBIAS);
    const int tig = lane & 3, gid = lane >> 2;
    const uint32_t bRow  = ((lane & 7) + ((lane & 16) >> 1));
    const uint32_t b1H = smb + MB1H + bRow * 144 + (lane & 8) * 2;
    const uint32_t b2H = smb + MB2H + bRow * 144 + (lane & 8) * 2;

    const uint4* et4 = (const uint4*)g_et;
    const int NCH = NE / 16;
    int gw = blockIdx.x * 8 + wid;
    int nw = gridDim.x * 8;

    for (int chunk = gw; chunk < NCH; chunk += nw) {
        int base16 = chunk * 16;
        int s = 0, d = 0;
        if (lane < 16) { s = ei[base16 + lane]; d = ei[NE + base16 + lane]; }
        int s0 = __shfl_sync(0xffffffffu, s, gid), s1 = __shfl_sync(0xffffffffu, s, gid + 8);
        int d0 = __shfl_sync(0xffffffffu, d, gid), d1 = __shfl_sync(0xffffffffu, d, gid + 8);

        uint4 A[4];
        #pragma unroll
        for (int kt = 0; kt < 4; kt++)
            A[kt] = __ldg(et4 + (size_t)chunk * 128 + kt * 32 + lane);

        float acc[8][4];
        #pragma unroll
        for (int n = 0; n < 8; n++)
            #pragma unroll
            for (int j = 0; j < 4; j++) acc[n][j] = 0.f;

        #pragma unroll
        for (int kt = 0; kt < 4; kt++) {
            uint32_t ah[4] = {A[kt].x, A[kt].y, A[kt].z, A[kt].w};
            #pragma unroll
            for (int ng = 0; ng < 4; ng++) {
                uint32_t bh[4];
                LDSM4(bh, b1H + ng * 16 * 144 + kt * 32);
                MMA16816(acc[2 * ng],     ah, bh[0], bh[1]);
                MMA16816(acc[2 * ng + 1], ah, bh[2], bh[3]);
            }
        }

        unsigned P0w[8], P1w[8], Q0w[8], Q1w[8];
        {
            const uint4* p0 = (const uint4*)(g_psh + s0 * 32 + tig * 8);
            const uint4* p1 = (const uint4*)(g_psh + s1 * 32 + tig * 8);
            const uint4* q0 = (const uint4*)(g_pdh + d0 * 32 + tig * 8);
            const uint4* q1 = (const uint4*)(g_pdh + d1 * 32 + tig * 8);
            uint4 a, b;
            a = __ldg(p0); b = __ldg(p0 + 1);
            P0w[0]=a.x; P0w[1]=a.y; P0w[2]=a.z; P0w[3]=a.w;
            P0w[4]=b.x; P0w[5]=b.y; P0w[6]=b.z; P0w[7]=b.w;
            a = __ldg(p1); b = __ldg(p1 + 1);
            P1w[0]=a.x; P1w[1]=a.y; P1w[2]=a.z; P1w[3]=a.w;
            P1w[4]=b.x; P1w[5]=b.y; P1w[6]=b.z; P1w[7]=b.w;
            a = __ldg(q0); b = __ldg(q0 + 1);
            Q0w[0]=a.x; Q0w[1]=a.y; Q0w[2]=a.z; Q0w[3]=a.w;
            Q0w[4]=b.x; Q0w[5]=b.y; Q0w[6]=b.z; Q0w[7]=b.w;
            a = __ldg(q1); b = __ldg(q1 + 1);
            Q1w[0]=a.x; Q1w[1]=a.y; Q1w[2]=a.z; Q1w[3]=a.w;
            Q1w[4]=b.x; Q1w[5]=b.y; Q1w[6]=b.z; Q1w[7]=b.w;
        }

        float acc2[8][4];
        #pragma unroll
        for (int n = 0; n < 8; n++)
            #pragma unroll
            for (int j = 0; j < 4; j++) acc2[n][j] = 0.f;

        #pragma unroll
        for (int kt = 0; kt < 4; kt++) {
            uint32_t a2[4];
            #pragma unroll
            for (int j = 0; j < 2; j++) {
                int nt = 2 * kt + j;
                float2 p0v = h2f(P0w[nt]), q0v = h2f(Q0w[nt]);
                float2 p1v = h2f(P1w[nt]), q1v = h2f(Q1w[nt]);
                float v0 = fmaxf(acc[nt][0] + p0v.x + q0v.x, 0.f);
                float v1 = fmaxf(acc[nt][1] + p0v.y + q0v.y, 0.f);
                float v2 = fmaxf(acc[nt][2] + p1v.x + q1v.x, 0.f);
                float v3 = fmaxf(acc[nt][3] + p1v.y + q1v.y, 0.f);
                a2[2 * j]     = pack_h2(v0, v1);
                a2[2 * j + 1] = pack_h2(v2, v3);
            }
            #pragma unroll
            for (int ng = 0; ng < 4; ng++) {
                uint32_t bh[4];
                LDSM4(bh, b2H + ng * 16 * 144 + kt * 32);
                MMA16816(acc2[2 * ng],     a2, bh[0], bh[1]);
                MMA16816(acc2[2 * ng + 1], a2, bh[2], bh[3]);
            }
        }

        float* plo = g_agg + (size_t)d0 * H + tig * 4;
        float* phi = g_agg + (size_t)d1 * H + tig * 4;
        #pragma unroll
        for (int m = 0; m < 4; m++) {
            float2 be = *(const float2*)(b2s + (2 * m) * 8 + 2 * tig);
            float2 bo = *(const float2*)(b2s + (2 * m + 1) * 8 + 2 * tig);
            float e0 = acc2[2 * m][0] + be.x, e1 = acc2[2 * m][1] + be.y;
            float o0 = acc2[2 * m + 1][0] + bo.x, o1 = acc2[2 * m + 1][1] + bo.y;
            asm volatile("red.global.add.v4.f32 [%0], {%1,%2,%3,%4};"
                :: "l"(plo + m * 16), "f"(e0), "f"(e1), "f"(o0), "f"(o1) : "memory");
            float e2 = acc2[2 * m][2] + be.x, e3 = acc2[2 * m][3] + be.y;
            float o2 = acc2[2 * m + 1][2] + bo.x, o3 = acc2[2 * m + 1][3] + bo.y;
            asm volatile("red.global.add.v4.f32 [%0], {%1,%2,%3,%4};"
                :: "l"(phi + m * 16), "f"(e2), "f"(e3), "f"(o2), "f"(o3) : "memory");
        }
        __syncwarp();
    }
}

// ============================================================
// k_upd_mma: hi-only weights; reads agg (inv perm), re-zeroes
// ============================================================
#define UB1H 0
#define UB2H 17408
#define UBIAS 26624
#define UA 27136
#define UPD_SMEM (27136 + 8 * 4352)

__global__ void __launch_bounds__(256, 2) k_upd_mma(
        const float* __restrict__ W1, const float* __restrict__ b1,
        const float* __restrict__ W2, const float* __restrict__ b2,
        int si, int di) {
    extern __shared__ char sm[];
    const uint32_t smb = smem_u32(sm);
    int tid = threadIdx.x, lane = tid & 31, wid = tid >> 5;

    for (int i = tid; i < 128 * 64; i += blockDim.x) {
        int k = i >> 6, n = i & 63;
        ((__half*)(sm + UB1H))[n * 136 + k] = __float2half_rn(W1[i]);
    }
    for (int i = tid; i < 64 * 64; i += blockDim.x) {
        int k = i >> 6, n = i & 63;
        ((__half*)(sm + UB2H))[n * 72 + k] = __float2half_rn(W2[i]);
    }
    if (tid < 64) {
        ((float*)(sm + UBIAS))[tid] = b1[tid];
        ((float*)(sm + UBIAS + 256))[tid] = b2[tid];
    }
    __syncthreads();

    const float* b1s = (const float*)(sm + UBIAS);
    const float* b2s = (const float*)(sm + UBIAS + 256);
    float* xd = g_xb[di];

    const int tig = lane & 3, gid = lane >> 2;
    const int wagg = (2 * (lane >> 3) + (lane & 1)) * 4 + ((lane >> 1) & 3);
    const uint32_t aRow = smb + UA + wid * 4352 + (lane & 15) * 272 + (lane & 16);
    const uint32_t bRow  = ((lane & 7) + ((lane & 16) >> 1));
    const uint32_t b1AddrH = smb + UB1H + bRow * 272 + (lane & 8) * 2;
    const uint32_t b2AddrH = smb + UB2H + bRow * 144 + (lane & 8) * 2;
    char* aRowPtr = sm + UA + wid * 4352;

    int gw = blockIdx.x * 8 + wid;
    int nw = gridDim.x * 8;
    for (int chunk = gw; chunk < NN / 16; chunk += nw) {
        int base16 = chunk * 16;
        #pragma unroll 4
        for (int t = 0; t < 16; t++) {
            int n = base16 + t;
            float2* agp = (float2*)(g_agg + (size_t)n * H) + lane;
            float2 ag = *agp;
            *agp = make_float2(0.f, 0.f);
            char* rp = aRowPtr + t * 272;
            ((unsigned*)rp)[lane]         = g_xf[n * 32 + lane];
            ((unsigned*)(rp + 128))[wagg] = pack_h2(ag.x, ag.y);
        }
        __syncwarp();

        float acc[8][4];
        #pragma unroll
        for (int n = 0; n < 8; n++)
            #pragma unroll
            for (int j = 0; j < 4; j++) acc[n][j] = 0.f;

        #pragma unroll 2
        for (int kt = 0; kt < 8; kt++) {
            uint32_t ah[4];
            LDSM4(ah, aRow + kt * 32);
            #pragma unroll
            for (int ng = 0; ng < 4; ng++) {
                uint32_t bh[4];
                LDSM4(bh, b1AddrH + ng * 16 * 272 + kt * 32);
                MMA16816(acc[2 * ng],     ah, bh[0], bh[1]);
                MMA16816(acc[2 * ng + 1], ah, bh[2], bh[3]);
            }
        }

        float acc2[8][4];
        #pragma unroll
        for (int n = 0; n < 8; n++)
            #pragma unroll
            for (int j = 0; j < 4; j++) acc2[n][j] = 0.f;

        #pragma unroll
        for (int kt = 0; kt < 4; kt++) {
            uint32_t a2[4];
            #pragma unroll
            for (int j = 0; j < 2; j++) {
                int nt = kt * 2 + j;
                float2 bb = *(const float2*)(b1s + nt * 8 + 2 * tig);
                float v0 = fmaxf(acc[nt][0] + bb.x, 0.f);
                float v1 = fmaxf(acc[nt][1] + bb.y, 0.f);
                float v2 = fmaxf(acc[nt][2] + bb.x, 0.f);
                float v3 = fmaxf(acc[nt][3] + bb.y, 0.f);
                a2[2 * j]     = pack_h2(v0, v1);
                a2[2 * j + 1] = pack_h2(v2, v3);
            }
            #pragma unroll
            for (int ng = 0; ng < 4; ng++) {
                uint32_t bh[4];
                LDSM4(bh, b2AddrH + ng * 16 * 144 + kt * 32);
                MMA16816(acc2[2 * ng],     a2, bh[0], bh[1]);
                MMA16816(acc2[2 * ng + 1], a2, bh[2], bh[3]);
            }
        }

        int n0 = base16 + gid, n1 = base16 + gid + 8;
        #pragma unroll
        for (int nt = 0; nt < 8; nt++) {
            float2 bb = *(const float2*)(b2s + nt * 8 + 2 * tig);
            float f0 = acc2[nt][0] + bb.x, f1 = acc2[nt][1] + bb.y;
            float f2 = acc2[nt][2] + bb.x, f3 = acc2[nt][3] + bb.y;
            *(float2*)(xd + (size_t)n0 * H + nt * 8 + 2 * tig) = make_float2(f0, f1);
            *(float2*)(xd + (size_t)n1 * H + nt * 8 + 2 * tig) = make_float2(f2, f3);
            g_xf[n0 * 32 + nt * 4 + tig] = pack_h2(f0, f1);
            g_xf[n1 * 32 + nt * 4 + tig] = pack_h2(f2, f3);
        }
        __syncwarp();
    }
}

// ============================================================
// k_enc_edge_mma: hi-only weights; writes e fp16 A-fragment order
// ============================================================
#define EBH 0
#define EBIAS 9216
#define EA 9472
#define ENC_SMEM (9472 + 8 * 2304)

__global__ void __launch_bounds__(256) k_enc_edge_mma(const float* __restrict__ ef,
        const float* __restrict__ W, const float* __restrict__ b) {
    extern __shared__ char sm[];
    const uint32_t smb = smem_u32(sm);
    int tid = threadIdx.x, lane = tid & 31, wid = tid >> 5;

    for (int i = tid; i < 64 * 64; i += blockDim.x) {
        int k = i >> 6, n = i & 63;
        ((__half*)(sm + EBH))[n * 72 + k] = __float2half_rn(W[i]);
    }
    if (tid < 64) ((float*)(sm + EBIAS))[tid] = b[tid];
    __syncthreads();

    const float* bs = (const float*)(sm + EBIAS);
    const int tig = lane & 3;
    const int gi = lane >> 2;
    const uint32_t aRow = smb + EA + wid * 2304 + (lane & 15) * 144 + (lane & 16);
    const uint32_t bRow  = ((lane & 7) + ((lane & 16) >> 1));
    const uint32_t bAddrH = smb + EBH + bRow * 144 + (lane & 8) * 2;
    char* aRowPtr = sm + EA + wid * 2304;

    int gw = blockIdx.x * 8 + wid;
    int nw = gridDim.x * 8;
    for (int chunk = gw; chunk < NE / 16; chunk += nw) {
        int base16 = chunk * 16;
        #pragma unroll 4
        for (int t = 0; t < 16; t++) {
            float2 v = ((const float2*)(ef + (size_t)(base16 + t) * H))[lane];
            ((unsigned*)(aRowPtr + t * 144))[lane] = pack_h2(v.x, v.y);
        }
        __syncwarp();

        float acc[8][4];
        #pragma unroll
        for (int n = 0; n < 8; n++)
            #pragma unroll
            for (int j = 0; j < 4; j++) acc[n][j] = 0.f;

        #pragma unroll
        for (int kt = 0; kt < 4; kt++) {
            uint32_t ah[4];
            LDSM4(ah, aRow + kt * 32);
            #pragma unroll
            for (int ng = 0; ng < 4; ng++) {
                uint32_t bh[4];
                LDSM4(bh, bAddrH + ng * 16 * 144 + kt * 32);
                MMA16816(acc[2 * ng],     ah, bh[0], bh[1]);
                MMA16816(acc[2 * ng + 1], ah, bh[2], bh[3]);
            }
        }

        unsigned* de = g_et + (size_t)chunk * 512;
        #pragma unroll
        for (int nt = 0; nt < 8; nt++) {
            float2 bb = *(const float2*)(bs + nt * 8 + 2 * tig);
            float f0 = acc[nt][0] + bb.x, f1 = acc[nt][1] + bb.y;
            float f2 = acc[nt][2] + bb.x, f3 = acc[nt][3] + bb.y;
            int idx = (nt >> 1) * 128 + (gi * 4 + tig) * 4 + 2 * (nt & 1);
            de[idx]     = pack_h2(f0, f1);
            de[idx + 1] = pack_h2(f2, f3);
        }
        __syncwarp();
    }
}

// ============================================================
// k_enc_node: scalar f32x2; writes fp32 x + fp16 x
// ============================================================
__device__ __forceinline__ void ffma2(ull& d, ull a, ull b) {
    asm("fma.rn.f32x2 %0, %1, %2, %0;" : "+l"(d) : "l"(a), "l"(b));
}
__device__ __forceinline__ float fin(ull a, float b) {
    return __uint_as_float((unsigned)a) + __uint_as_float((unsigned)(a >> 32)) + b;
}

__global__ void __launch_bounds__(256) k_enc_node(const float* __restrict__ nf,
        const float* __restrict__ W, const float* __restrict__ b) {
    extern __shared__ float smf[];
    float* Wp   = smf;
    float* winb = Wp + 8320;
    int tid = threadIdx.x;
    for (int i = tid; i < 128 * 64; i += 256) {
        int k = i >> 6, c = i & 63;
        Wp[(c >> 1) * 260 + (k >> 1) * 4 + ((c & 1) << 1) + (k & 1)] = W[i];
    }
    __syncthreads();
    int lane = tid & 31, wid = tid >> 5;
    float2 bb = ((const float2*)b)[lane];
    float* win = winb + wid * 8 * ND;
    const ulonglong2* wl = (const ulonglong2*)(Wp + (size_t)lane * 260);
    int gw = blockIdx.x * 8 + wid;
    int nw = gridDim.x * 8;
    for (int base = gw * 8; base < NN; base += nw * 8) {
        #pragma unroll
        for (int t = 0; t < 8; t++) {
            float4 v = *(const float4*)(nf + (size_t)(base + t) * ND + lane * 4);
            *(float4*)(win + t * ND + lane * 4) = v;
        }
        __syncwarp();
        ull a0[8], a1[8];
        #pragma unroll
        for (int t = 0; t < 8; t++) { a0[t] = 0ull; a1[t] = 0ull; }
        #pragma unroll 4
        for (int c = 0; c < 32; c++) {
            ulonglong2 wA = wl[2 * c];
            ulonglong2 wB = wl[2 * c + 1];
            #pragma unroll
            for (int t = 0; t < 8; t++) {
                ulonglong2 v = ((const ulonglong2*)(win + t * ND))[c];
                ffma2(a0[t], wA.x, v.x); ffma2(a1[t], wA.y, v.x);
                ffma2(a0[t], wB.x, v.y); ffma2(a1[t], wB.y, v.y);
            }
        }
        #pragma unroll
        for (int t = 0; t < 8; t++) {
            float o0 = fin(a0[t], bb.x);
            float o1 = fin(a1[t], bb.y);
            int n = base + t;
            *(float2*)(g_xb[0] + (size_t)n * H + 2 * lane) = make_float2(o0, o1);
            g_xf[n * 32 + lane] = pack_h2(o0, o1);
        }
        __syncwarp();
    }
}

__global__ void k_con(const float* __restrict__ W1, const float* __restrict__ b1,
                      const float* __restrict__ w2, const float* __restrict__ b2,
                      int si, float* __restrict__ out) {
    __shared__ float Ws[H * H];
    __shared__ float bs[H];
    __shared__ float w2s[H];
    __shared__ float xb[8][H];
    __shared__ float b2v;
    int tid = threadIdx.x;
    for (int i = tid; i < H * H; i += blockDim.x) Ws[i] = W1[i];
    if (tid < H) { bs[tid] = b1[tid]; w2s[tid] = w2[tid]; }
    if (tid == 0) b2v = b2[0];
    __syncthreads();
    const float* xs = g_xb[si];
    int lane = tid & 31, wid = tid >> 5;
    int gw = blockIdx.x * 8 + wid;
    int nw = gridDim.x * 8;
    for (int n = gw; n < NN; n += nw) {
        float xv0 = xs[(size_t)n * H + lane];
        float xv1 = xs[(size_t)n * H + lane + 32];
        out[(size_t)n * H + lane]      = xv0;
        out[(size_t)n * H + lane + 32] = xv1;
        xb[wid][lane]      = xv0;
        xb[wid][lane + 32] = xv1;
        __syncwarp();
        float a0 = bs[lane], a1 = bs[lane + 32];
        #pragma unroll 4
        for (int k = 0; k < H; k++) {
            float v = xb[wid][k];
            a0 += v * Ws[k * H + lane];
            a1 += v * Ws[k * H + lane + 32];
        }
        float p = fmaxf(a0, 0.f) * w2s[lane] + fmaxf(a1, 0.f) * w2s[lane + 32];
        #pragma unroll
        for (int o = 16; o; o >>= 1) p += __shfl_xor_sync(0xffffffffu, p, o);
        if (lane == 0)
            out[(size_t)NN * H + n] = 1.f / (1.f + expf(-(p + b2v)));
        __syncwarp();
    }
}

extern "C" void kernel_launch(void* const* d_in, const int* in_sizes, int n_in,
                              void* d_out, int out_size) {
    const float* nf  = (const float*)d_in[0];
    const float* ef  = (const float*)d_in[1];
    const int*   ei  = (const int*)d_in[2];
    const float* enW = (const float*)d_in[3];
    const float* enb = (const float*)d_in[4];
    const float* eeW = (const float*)d_in[5];
    const float* eeb = (const float*)d_in[6];
    const float* mW1 = (const float*)d_in[7];
    const float* mb1 = (const float*)d_in[8];
    const float* mW2 = (const float*)d_in[9];
    const float* mb2 = (const float*)d_in[10];
    const float* uW1 = (const float*)d_in[11];
    const float* ub1 = (const float*)d_in[12];
    const float* uW2 = (const float*)d_in[13];
    const float* ub2 = (const float*)d_in[14];
    const float* cW1 = (const float*)d_in[15];
    const float* cb1 = (const float*)d_in[16];
    const float* cW2 = (const float*)d_in[17];
    const float* cb2 = (const float*)d_in[18];
    float* out = (float*)d_out;

    int dev = 0, smc = 148;
    cudaGetDevice(&dev);
    cudaDeviceGetAttribute(&smc, cudaDevAttrMultiProcessorCount, dev);

    const int ENN_SMEM = (8320 + 8192) * 4;
    cudaFuncSetAttribute(k_pre,          cudaFuncAttributeMaxDynamicSharedMemorySize, PRE_SMEM);
    cudaFuncSetAttribute(k_msg_mma,      cudaFuncAttributeMaxDynamicSharedMemorySize, MSG_SMEM);
    cudaFuncSetAttribute(k_upd_mma,      cudaFuncAttributeMaxDynamicSharedMemorySize, UPD_SMEM);
    cudaFuncSetAttribute(k_enc_edge_mma, cudaFuncAttributeMaxDynamicSharedMemorySize, ENC_SMEM);
    cudaFuncSetAttribute(k_enc_node,     cudaFuncAttributeMaxDynamicSharedMemorySize, ENN_SMEM);

    k_enc_node<<<smc * 2, 256, ENN_SMEM>>>(nf, enW, enb);
    k_enc_edge_mma<<<smc * 2, 256, ENC_SMEM>>>(ef, eeW, eeb);

    int cur = 0;
    for (int l = 0; l < 3; l++) {
        k_pre<<<smc * 2, 256, PRE_SMEM>>>(mW1 + (size_t)l * 192 * H, mb1 + l * H);
        k_msg_mma<<<smc * 2, 256, MSG_SMEM>>>(ei,
                                              mW1 + (size_t)l * 192 * H,
                                              mW2 + (size_t)l * H * H, mb2 + l * H);
        k_upd_mma<<<smc * 2, 256, UPD_SMEM>>>(uW1 + (size_t)l * 128 * H, ub1 + l * H,
                                              uW2 + (size_t)l * H * H,   ub2 + l * H,
                                              cur, 1 - cur);
        cur = 1 - cur;
    }
    k_con<<<1184, 256>>>(cW1, cb1, cW2, cb2, cur, out);
}

// round 16
// speedup vs baseline: 1.5008x; 1.0373x over previous
#include <cuda_runtime.h>
#include <cuda_fp16.h>
#include <math.h>
#include <cstdint>

#define NN 50000
#define NE 800000
#define H  64
#define ND 128

__device__ float g_xb[2][NN * H];
__device__ float g_agg[NN * H];              // PERMUTED cols
__device__ unsigned g_psh[NN * 32];          // Ps fp16 packed, word = tig*8 + nt
__device__ unsigned g_pdh[NN * 32];          // Pd fp16 packed
__device__ unsigned g_et[(size_t)NE * 32];   // e fp16 in MMA A-fragment order
__device__ unsigned g_xf[NN * 32];           // x fp16 (2 cols/word)

typedef unsigned long long ull;

__device__ __forceinline__ uint32_t smem_u32(const void* p) {
    uint32_t a;
    asm("{ .reg .u64 t; cvta.to.shared.u64 t, %1; cvt.u32.u64 %0, t; }" : "=r"(a) : "l"(p));
    return a;
}

#define LDSM4(r, addr) \
    asm volatile("ldmatrix.sync.aligned.m8n8.x4.shared.b16 {%0,%1,%2,%3}, [%4];" \
        : "=r"((r)[0]), "=r"((r)[1]), "=r"((r)[2]), "=r"((r)[3]) : "r"(addr))

#define MMA16816(c, a, b0v, b1v) \
    asm volatile("mma.sync.aligned.m16n8k16.row.col.f32.f16.f16.f32 " \
        "{%0,%1,%2,%3},{%4,%5,%6,%7},{%8,%9},{%0,%1,%2,%3};" \
        : "+f"((c)[0]), "+f"((c)[1]), "+f"((c)[2]), "+f"((c)[3]) \
        : "r"((a)[0]), "r"((a)[1]), "r"((a)[2]), "r"((a)[3]), "r"(b0v), "r"(b1v))

__device__ __forceinline__ unsigned pack_h2(float a, float b) {
    __half2 t = __floats2half2_rn(a, b);
    return *reinterpret_cast<unsigned*>(&t);
}
__device__ __forceinline__ float2 h2f(unsigned u) {
    return __half22float2(*reinterpret_cast<__half2*>(&u));
}

// ============================================================
// k_pre: Ps/Pd for layer 0 only (fp16 out, hi-only W); zeroes agg
// ============================================================
#define PBSH 0
#define PBDH 9216
#define PBIAS 18432
#define PA 18688
#define PRE_SMEM (18688 + 8 * 2304)

__global__ void __launch_bounds__(256) k_pre(const float* __restrict__ W1,
                                             const float* __restrict__ b1) {
    extern __shared__ char sm[];
    const uint32_t smb = smem_u32(sm);
    int tid = threadIdx.x, lane = tid & 31, wid = tid >> 5;

    for (int i = tid; i < 64 * 64; i += blockDim.x) {
        int k = i >> 6, n = i & 63;
        ((__half*)(sm + PBSH))[n * 72 + k] = __float2half_rn(W1[k * 64 + n]);
        ((__half*)(sm + PBDH))[n * 72 + k] = __float2half_rn(W1[(128 + k) * 64 + n]);
    }
    if (tid < 64) ((float*)(sm + PBIAS))[tid] = b1[tid];
    __syncthreads();

    const float* b1s = (const float*)(sm + PBIAS);
    const int tig = lane & 3, gid = lane >> 2;
    const uint32_t aRow = smb + PA + wid * 2304 + (lane & 15) * 144 + (lane & 16);
    const uint32_t bRow  = ((lane & 7) + ((lane & 16) >> 1));
    const uint32_t bsH = smb + PBSH + bRow * 144 + (lane & 8) * 2;
    const uint32_t bdH = smb + PBDH + bRow * 144 + (lane & 8) * 2;
    char* aRowPtr = sm + PA + wid * 2304;

    int gw = blockIdx.x * 8 + wid;
    int nw = gridDim.x * 8;
    for (int chunk = gw; chunk < NN / 16; chunk += nw) {
        int base16 = chunk * 16;
        #pragma unroll 4
        for (int t = 0; t < 16; t++)
            ((unsigned*)(aRowPtr + t * 144))[lane] = g_xf[(base16 + t) * 32 + lane];
        __syncwarp();

        float as[8][4], ad[8][4];
        #pragma unroll
        for (int n = 0; n < 8; n++)
            #pragma unroll
            for (int j = 0; j < 4; j++) { as[n][j] = 0.f; ad[n][j] = 0.f; }

        #pragma unroll
        for (int kt = 0; kt < 4; kt++) {
            uint32_t ah[4];
            LDSM4(ah, aRow + kt * 32);
            #pragma unroll
            for (int ng = 0; ng < 4; ng++) {
                uint32_t bh[4];
                LDSM4(bh, bsH + ng * 16 * 144 + kt * 32);
                MMA16816(as[2 * ng],     ah, bh[0], bh[1]);
                MMA16816(as[2 * ng + 1], ah, bh[2], bh[3]);
                LDSM4(bh, bdH + ng * 16 * 144 + kt * 32);
                MMA16816(ad[2 * ng],     ah, bh[0], bh[1]);
                MMA16816(ad[2 * ng + 1], ah, bh[2], bh[3]);
            }
        }

        int n0 = base16 + gid, n1 = base16 + gid + 8;
        unsigned ps0[8], ps1[8], pd0[8], pd1[8];
        #pragma unroll
        for (int nt = 0; nt < 8; nt++) {
            float2 bb = *(const float2*)(b1s + nt * 8 + 2 * tig);
            int c = nt * 8 + 2 * tig;
            ps0[nt] = pack_h2(as[nt][0] + bb.x, as[nt][1] + bb.y);
            ps1[nt] = pack_h2(as[nt][2] + bb.x, as[nt][3] + bb.y);
            pd0[nt] = pack_h2(ad[nt][0], ad[nt][1]);
            pd1[nt] = pack_h2(ad[nt][2], ad[nt][3]);
            *(float2*)(g_agg + (size_t)n0 * H + c) = make_float2(0.f, 0.f);
            *(float2*)(g_agg + (size_t)n1 * H + c) = make_float2(0.f, 0.f);
        }
        *(uint4*)(g_psh + n0 * 32 + tig * 8)     = make_uint4(ps0[0], ps0[1], ps0[2], ps0[3]);
        *(uint4*)(g_psh + n0 * 32 + tig * 8 + 4) = make_uint4(ps0[4], ps0[5], ps0[6], ps0[7]);
        *(uint4*)(g_psh + n1 * 32 + tig * 8)     = make_uint4(ps1[0], ps1[1], ps1[2], ps1[3]);
        *(uint4*)(g_psh + n1 * 32 + tig * 8 + 4) = make_uint4(ps1[4], ps1[5], ps1[6], ps1[7]);
        *(uint4*)(g_pdh + n0 * 32 + tig * 8)     = make_uint4(pd0[0], pd0[1], pd0[2], pd0[3]);
        *(uint4*)(g_pdh + n0 * 32 + tig * 8 + 4) = make_uint4(pd0[4], pd0[5], pd0[6], pd0[7]);
        *(uint4*)(g_pdh + n1 * 32 + tig * 8)     = make_uint4(pd1[0], pd1[1], pd1[2], pd1[3]);
        *(uint4*)(g_pdh + n1 * 32 + tig * 8 + 4) = make_uint4(pd1[4], pd1[5], pd1[6], pd1[7]);
        __syncwarp();
    }
}

// ============================================================
// k_msg_mma: unchanged from R15 (verified)
// ============================================================
#define MB1H 0
#define MB2H 9216
#define MBIAS 18432
#define MSG_SMEM 18944

__global__ void __launch_bounds__(256, 2) k_msg_mma(const int* __restrict__ ei,
        const float* __restrict__ W1, const float* __restrict__ W2,
        const float* __restrict__ b2) {
    extern __shared__ char sm[];
    const uint32_t smb = smem_u32(sm);
    int tid = threadIdx.x, lane = tid & 31, wid = tid >> 5;

    for (int i = tid; i < 64 * 64; i += blockDim.x) {
        int k = i >> 6, n = i & 63;
        ((__half*)(sm + MB1H))[n * 72 + k] = __float2half_rn(W1[(64 + k) * 64 + n]);
        ((__half*)(sm + MB2H))[n * 72 + k] = __float2half_rn(W2[k * 64 + n]);
    }
    if (tid < 64) ((float*)(sm + MBIAS))[tid] = b2[tid];
    __syncthreads();

    const float* b2s = (const float*)(sm + MBIAS);
    const int tig = lane & 3, gid = lane >> 2;
    const uint32_t bRow  = ((lane & 7) + ((lane & 16) >> 1));
    const uint32_t b1H = smb + MB1H + bRow * 144 + (lane & 8) * 2;
    const uint32_t b2H = smb + MB2H + bRow * 144 + (lane & 8) * 2;

    const uint4* et4 = (const uint4*)g_et;
    const int NCH = NE / 16;
    int gw = blockIdx.x * 8 + wid;
    int nw = gridDim.x * 8;

    for (int chunk = gw; chunk < NCH; chunk += nw) {
        int base16 = chunk * 16;
        int s = 0, d = 0;
        if (lane < 16) { s = ei[base16 + lane]; d = ei[NE + base16 + lane]; }
        int s0 = __shfl_sync(0xffffffffu, s, gid), s1 = __shfl_sync(0xffffffffu, s, gid + 8);
        int d0 = __shfl_sync(0xffffffffu, d, gid), d1 = __shfl_sync(0xffffffffu, d, gid + 8);

        uint4 A[4];
        #pragma unroll
        for (int kt = 0; kt < 4; kt++)
            A[kt] = __ldg(et4 + (size_t)chunk * 128 + kt * 32 + lane);

        float acc[8][4];
        #pragma unroll
        for (int n = 0; n < 8; n++)
            #pragma unroll
            for (int j = 0; j < 4; j++) acc[n][j] = 0.f;

        #pragma unroll
        for (int kt = 0; kt < 4; kt++) {
            uint32_t ah[4] = {A[kt].x, A[kt].y, A[kt].z, A[kt].w};
            #pragma unroll
            for (int ng = 0; ng < 4; ng++) {
                uint32_t bh[4];
                LDSM4(bh, b1H + ng * 16 * 144 + kt * 32);
                MMA16816(acc[2 * ng],     ah, bh[0], bh[1]);
                MMA16816(acc[2 * ng + 1], ah, bh[2], bh[3]);
            }
        }

        unsigned P0w[8], P1w[8], Q0w[8], Q1w[8];
        {
            const uint4* p0 = (const uint4*)(g_psh + s0 * 32 + tig * 8);
            const uint4* p1 = (const uint4*)(g_psh + s1 * 32 + tig * 8);
            const uint4* q0 = (const uint4*)(g_pdh + d0 * 32 + tig * 8);
            const uint4* q1 = (const uint4*)(g_pdh + d1 * 32 + tig * 8);
            uint4 a, b;
            a = __ldg(p0); b = __ldg(p0 + 1);
            P0w[0]=a.x; P0w[1]=a.y; P0w[2]=a.z; P0w[3]=a.w;
            P0w[4]=b.x; P0w[5]=b.y; P0w[6]=b.z; P0w[7]=b.w;
            a = __ldg(p1); b = __ldg(p1 + 1);
            P1w[0]=a.x; P1w[1]=a.y; P1w[2]=a.z; P1w[3]=a.w;
            P1w[4]=b.x; P1w[5]=b.y; P1w[6]=b.z; P1w[7]=b.w;
            a = __ldg(q0); b = __ldg(q0 + 1);
            Q0w[0]=a.x; Q0w[1]=a.y; Q0w[2]=a.z; Q0w[3]=a.w;
            Q0w[4]=b.x; Q0w[5]=b.y; Q0w[6]=b.z; Q0w[7]=b.w;
            a = __ldg(q1); b = __ldg(q1 + 1);
            Q1w[0]=a.x; Q1w[1]=a.y; Q1w[2]=a.z; Q1w[3]=a.w;
            Q1w[4]=b.x; Q1w[5]=b.y; Q1w[6]=b.z; Q1w[7]=b.w;
        }

        float acc2[8][4];
        #pragma unroll
        for (int n = 0; n < 8; n++)
            #pragma unroll
            for (int j = 0; j < 4; j++) acc2[n][j] = 0.f;

        #pragma unroll
        for (int kt = 0; kt < 4; kt++) {
            uint32_t a2[4];
            #pragma unroll
            for (int j = 0; j < 2; j++) {
                int nt = 2 * kt + j;
                float2 p0v = h2f(P0w[nt]), q0v = h2f(Q0w[nt]);
                float2 p1v = h2f(P1w[nt]), q1v = h2f(Q1w[nt]);
                float v0 = fmaxf(acc[nt][0] + p0v.x + q0v.x, 0.f);
                float v1 = fmaxf(acc[nt][1] + p0v.y + q0v.y, 0.f);
                float v2 = fmaxf(acc[nt][2] + p1v.x + q1v.x, 0.f);
                float v3 = fmaxf(acc[nt][3] + p1v.y + q1v.y, 0.f);
                a2[2 * j]     = pack_h2(v0, v1);
                a2[2 * j + 1] = pack_h2(v2, v3);
            }
            #pragma unroll
            for (int ng = 0; ng < 4; ng++) {
                uint32_t bh[4];
                LDSM4(bh, b2H + ng * 16 * 144 + kt * 32);
                MMA16816(acc2[2 * ng],     a2, bh[0], bh[1]);
                MMA16816(acc2[2 * ng + 1], a2, bh[2], bh[3]);
            }
        }

        float* plo = g_agg + (size_t)d0 * H + tig * 4;
        float* phi = g_agg + (size_t)d1 * H + tig * 4;
        #pragma unroll
        for (int m = 0; m < 4; m++) {
            float2 be = *(const float2*)(b2s + (2 * m) * 8 + 2 * tig);
            float2 bo = *(const float2*)(b2s + (2 * m + 1) * 8 + 2 * tig);
            float e0 = acc2[2 * m][0] + be.x, e1 = acc2[2 * m][1] + be.y;
            float o0 = acc2[2 * m + 1][0] + bo.x, o1 = acc2[2 * m + 1][1] + bo.y;
            asm volatile("red.global.add.v4.f32 [%0], {%1,%2,%3,%4};"
                :: "l"(plo + m * 16), "f"(e0), "f"(e1), "f"(o0), "f"(o1) : "memory");
            float e2 = acc2[2 * m][2] + be.x, e3 = acc2[2 * m][3] + be.y;
            float o2 = acc2[2 * m + 1][2] + bo.x, o3 = acc2[2 * m + 1][3] + bo.y;
            asm volatile("red.global.add.v4.f32 [%0], {%1,%2,%3,%4};"
                :: "l"(phi + m * 16), "f"(e2), "f"(e3), "f"(o2), "f"(o3) : "memory");
        }
        __syncwarp();
    }
}

// ============================================================
// k_upd_mma: hi-only weights; FUSED next-layer Ps/Pd (do_pre)
//            final layer writes x to `outp`
// ============================================================
#define UB1H 0
#define UB2H 17408
#define UNW1S 26624
#define UNW1D 35840
#define UBIAS 45056
#define UA 45824
#define UPD_SMEM (45824 + 8 * 4352)   // 80640

__global__ void __launch_bounds__(256, 2) k_upd_mma(
        const float* __restrict__ W1, const float* __restrict__ b1,
        const float* __restrict__ W2, const float* __restrict__ b2,
        const float* __restrict__ nW1, const float* __restrict__ nb1,
        int si, int do_pre, float* __restrict__ outp) {
    extern __shared__ char sm[];
    const uint32_t smb = smem_u32(sm);
    int tid = threadIdx.x, lane = tid & 31, wid = tid >> 5;

    for (int i = tid; i < 128 * 64; i += blockDim.x) {
        int k = i >> 6, n = i & 63;
        ((__half*)(sm + UB1H))[n * 136 + k] = __float2half_rn(W1[i]);
    }
    for (int i = tid; i < 64 * 64; i += blockDim.x) {
        int k = i >> 6, n = i & 63;
        ((__half*)(sm + UB2H))[n * 72 + k] = __float2half_rn(W2[i]);
        if (do_pre) {
            ((__half*)(sm + UNW1S))[n * 72 + k] = __float2half_rn(nW1[k * 64 + n]);
            ((__half*)(sm + UNW1D))[n * 72 + k] = __float2half_rn(nW1[(128 + k) * 64 + n]);
        }
    }
    if (tid < 64) {
        ((float*)(sm + UBIAS))[tid] = b1[tid];
        ((float*)(sm + UBIAS + 256))[tid] = b2[tid];
        ((float*)(sm + UBIAS + 512))[tid] = do_pre ? nb1[tid] : 0.f;
    }
    __syncthreads();

    const float* b1s = (const float*)(sm + UBIAS);
    const float* b2s = (const float*)(sm + UBIAS + 256);
    const float* nb1s = (const float*)(sm + UBIAS + 512);
    float* xd = outp ? outp : g_xb[1 - si];

    const int tig = lane & 3, gid = lane >> 2;
    const int wagg = (2 * (lane >> 3) + (lane & 1)) * 4 + ((lane >> 1) & 3);
    const uint32_t aRow = smb + UA + wid * 4352 + (lane & 15) * 272 + (lane & 16);
    const uint32_t bRow  = ((lane & 7) + ((lane & 16) >> 1));
    const uint32_t b1AddrH = smb + UB1H + bRow * 272 + (lane & 8) * 2;
    const uint32_t b2AddrH = smb + UB2H + bRow * 144 + (lane & 8) * 2;
    const uint32_t nsH = smb + UNW1S + bRow * 144 + (lane & 8) * 2;
    const uint32_t ndH = smb + UNW1D + bRow * 144 + (lane & 8) * 2;
    char* aRowPtr = sm + UA + wid * 4352;

    int gw = blockIdx.x * 8 + wid;
    int nw = gridDim.x * 8;
    for (int chunk = gw; chunk < NN / 16; chunk += nw) {
        int base16 = chunk * 16;
        #pragma unroll 4
        for (int t = 0; t < 16; t++) {
            int n = base16 + t;
            float2* agp = (float2*)(g_agg + (size_t)n * H) + lane;
            float2 ag = *agp;
            *agp = make_float2(0.f, 0.f);
            char* rp = aRowPtr + t * 272;
            ((unsigned*)rp)[lane]         = g_xf[n * 32 + lane];
            ((unsigned*)(rp + 128))[wagg] = pack_h2(ag.x, ag.y);
        }
        __syncwarp();

        float acc[8][4];
        #pragma unroll
        for (int n = 0; n < 8; n++)
            #pragma unroll
            for (int j = 0; j < 4; j++) acc[n][j] = 0.f;

        #pragma unroll 2
        for (int kt = 0; kt < 8; kt++) {
            uint32_t ah[4];
            LDSM4(ah, aRow + kt * 32);
            #pragma unroll
            for (int ng = 0; ng < 4; ng++) {
                uint32_t bh[4];
                LDSM4(bh, b1AddrH + ng * 16 * 272 + kt * 32);
                MMA16816(acc[2 * ng],     ah, bh[0], bh[1]);
                MMA16816(acc[2 * ng + 1], ah, bh[2], bh[3]);
            }
        }

        float acc2[8][4];
        #pragma unroll
        for (int n = 0; n < 8; n++)
            #pragma unroll
            for (int j = 0; j < 4; j++) acc2[n][j] = 0.f;

        #pragma unroll
        for (int kt = 0; kt < 4; kt++) {
            uint32_t a2[4];
            #pragma unroll
            for (int j = 0; j < 2; j++) {
                int nt = kt * 2 + j;
                float2 bb = *(const float2*)(b1s + nt * 8 + 2 * tig);
                float v0 = fmaxf(acc[nt][0] + bb.x, 0.f);
                float v1 = fmaxf(acc[nt][1] + bb.y, 0.f);
                float v2 = fmaxf(acc[nt][2] + bb.x, 0.f);
                float v3 = fmaxf(acc[nt][3] + bb.y, 0.f);
                a2[2 * j]     = pack_h2(v0, v1);
                a2[2 * j + 1] = pack_h2(v2, v3);
            }
            #pragma unroll
            for (int ng = 0; ng < 4; ng++) {
                uint32_t bh[4];
                LDSM4(bh, b2AddrH + ng * 16 * 144 + kt * 32);
                MMA16816(acc2[2 * ng],     a2, bh[0], bh[1]);
                MMA16816(acc2[2 * ng + 1], a2, bh[2], bh[3]);
            }
        }

        int n0 = base16 + gid, n1 = base16 + gid + 8;
        uint32_t a2x[4][4];
        #pragma unroll
        for (int nt = 0; nt < 8; nt++) {
            float2 bb = *(const float2*)(b2s + nt * 8 + 2 * tig);
            float f0 = acc2[nt][0] + bb.x, f1 = acc2[nt][1] + bb.y;
            float f2 = acc2[nt][2] + bb.x, f3 = acc2[nt][3] + bb.y;
            *(float2*)(xd + (size_t)n0 * H + nt * 8 + 2 * tig) = make_float2(f0, f1);
            *(float2*)(xd + (size_t)n1 * H + nt * 8 + 2 * tig) = make_float2(f2, f3);
            unsigned w0 = pack_h2(f0, f1);
            unsigned w1 = pack_h2(f2, f3);
            g_xf[n0 * 32 + nt * 4 + tig] = w0;
            g_xf[n1 * 32 + nt * 4 + tig] = w1;
            a2x[nt >> 1][2 * (nt & 1)]     = w0;
            a2x[nt >> 1][2 * (nt & 1) + 1] = w1;
        }

        // fused next-layer Ps/Pd
        if (do_pre) {
            float as[8][4];
            #pragma unroll
            for (int n = 0; n < 8; n++)
                #pragma unroll
                for (int j = 0; j < 4; j++) as[n][j] = 0.f;
            #pragma unroll
            for (int kt = 0; kt < 4; kt++)
                #pragma unroll
                for (int ng = 0; ng < 4; ng++) {
                    uint32_t bh[4];
                    LDSM4(bh, nsH + ng * 16 * 144 + kt * 32);
                    MMA16816(as[2 * ng],     a2x[kt], bh[0], bh[1]);
                    MMA16816(as[2 * ng + 1], a2x[kt], bh[2], bh[3]);
                }
            unsigned w0[8], w1[8];
            #pragma unroll
            for (int nt = 0; nt < 8; nt++) {
                float2 bb = *(const float2*)(nb1s + nt * 8 + 2 * tig);
                w0[nt] = pack_h2(as[nt][0] + bb.x, as[nt][1] + bb.y);
                w1[nt] = pack_h2(as[nt][2] + bb.x, as[nt][3] + bb.y);
            }
            *(uint4*)(g_psh + n0 * 32 + tig * 8)     = make_uint4(w0[0], w0[1], w0[2], w0[3]);
            *(uint4*)(g_psh + n0 * 32 + tig * 8 + 4) = make_uint4(w0[4], w0[5], w0[6], w0[7]);
            *(uint4*)(g_psh + n1 * 32 + tig * 8)     = make_uint4(w1[0], w1[1], w1[2], w1[3]);
            *(uint4*)(g_psh + n1 * 32 + tig * 8 + 4) = make_uint4(w1[4], w1[5], w1[6], w1[7]);

            #pragma unroll
            for (int n = 0; n < 8; n++)
                #pragma unroll
                for (int j = 0; j < 4; j++) as[n][j] = 0.f;
            #pragma unroll
            for (int kt = 0; kt < 4; kt++)
                #pragma unroll
                for (int ng = 0; ng < 4; ng++) {
                    uint32_t bh[4];
                    LDSM4(bh, ndH + ng * 16 * 144 + kt * 32);
                    MMA16816(as[2 * ng],     a2x[kt], bh[0], bh[1]);
                    MMA16816(as[2 * ng + 1], a2x[kt], bh[2], bh[3]);
                }
            #pragma unroll
            for (int nt = 0; nt < 8; nt++) {
                w0[nt] = pack_h2(as[nt][0], as[nt][1]);
                w1[nt] = pack_h2(as[nt][2], as[nt][3]);
            }
            *(uint4*)(g_pdh + n0 * 32 + tig * 8)     = make_uint4(w0[0], w0[1], w0[2], w0[3]);
            *(uint4*)(g_pdh + n0 * 32 + tig * 8 + 4) = make_uint4(w0[4], w0[5], w0[6], w0[7]);
            *(uint4*)(g_pdh + n1 * 32 + tig * 8)     = make_uint4(w1[0], w1[1], w1[2], w1[3]);
            *(uint4*)(g_pdh + n1 * 32 + tig * 8 + 4) = make_uint4(w1[4], w1[5], w1[6], w1[7]);
        }
        __syncwarp();
    }
}

// ============================================================
// k_enc_edge_mma: unchanged from R15
// ============================================================
#define EBH 0
#define EBIAS 9216
#define EA 9472
#define ENC_SMEM (9472 + 8 * 2304)

__global__ void __launch_bounds__(256) k_enc_edge_mma(const float* __restrict__ ef,
        const float* __restrict__ W, const float* __restrict__ b) {
    extern __shared__ char sm[];
    const uint32_t smb = smem_u32(sm);
    int tid = threadIdx.x, lane = tid & 31, wid = tid >> 5;

    for (int i = tid; i < 64 * 64; i += blockDim.x) {
        int k = i >> 6, n = i & 63;
        ((__half*)(sm + EBH))[n * 72 + k] = __float2half_rn(W[i]);
    }
    if (tid < 64) ((float*)(sm + EBIAS))[tid] = b[tid];
    __syncthreads();

    const float* bs = (const float*)(sm + EBIAS);
    const int tig = lane & 3;
    const int gi = lane >> 2;
    const uint32_t aRow = smb + EA + wid * 2304 + (lane & 15) * 144 + (lane & 16);
    const uint32_t bRow  = ((lane & 7) + ((lane & 16) >> 1));
    const uint32_t bAddrH = smb + EBH + bRow * 144 + (lane & 8) * 2;
    char* aRowPtr = sm + EA + wid * 2304;

    int gw = blockIdx.x * 8 + wid;
    int nw = gridDim.x * 8;
    for (int chunk = gw; chunk < NE / 16; chunk += nw) {
        int base16 = chunk * 16;
        #pragma unroll 4
        for (int t = 0; t < 16; t++) {
            float2 v = ((const float2*)(ef + (size_t)(base16 + t) * H))[lane];
            ((unsigned*)(aRowPtr + t * 144))[lane] = pack_h2(v.x, v.y);
        }
        __syncwarp();

        float acc[8][4];
        #pragma unroll
        for (int n = 0; n < 8; n++)
            #pragma unroll
            for (int j = 0; j < 4; j++) acc[n][j] = 0.f;

        #pragma unroll
        for (int kt = 0; kt < 4; kt++) {
            uint32_t ah[4];
            LDSM4(ah, aRow + kt * 32);
            #pragma unroll
            for (int ng = 0; ng < 4; ng++) {
                uint32_t bh[4];
                LDSM4(bh, bAddrH + ng * 16 * 144 + kt * 32);
                MMA16816(acc[2 * ng],     ah, bh[0], bh[1]);
                MMA16816(acc[2 * ng + 1], ah, bh[2], bh[3]);
            }
        }

        unsigned* de = g_et + (size_t)chunk * 512;
        #pragma unroll
        for (int nt = 0; nt < 8; nt++) {
            float2 bb = *(const float2*)(bs + nt * 8 + 2 * tig);
            float f0 = acc[nt][0] + bb.x, f1 = acc[nt][1] + bb.y;
            float f2 = acc[nt][2] + bb.x, f3 = acc[nt][3] + bb.y;
            int idx = (nt >> 1) * 128 + (gi * 4 + tig) * 4 + 2 * (nt & 1);
            de[idx]     = pack_h2(f0, f1);
            de[idx + 1] = pack_h2(f2, f3);
        }
        __syncwarp();
    }
}

// ============================================================
// k_enc_node: scalar f32x2 (unchanged)
// ============================================================
__device__ __forceinline__ void ffma2(ull& d, ull a, ull b) {
    asm("fma.rn.f32x2 %0, %1, %2, %0;" : "+l"(d) : "l"(a), "l"(b));
}
__device__ __forceinline__ float fin(ull a, float b) {
    return __uint_as_float((unsigned)a) + __uint_as_float((unsigned)(a >> 32)) + b;
}

__global__ void __launch_bounds__(256) k_enc_node(const float* __restrict__ nf,
        const float* __restrict__ W, const float* __restrict__ b) {
    extern __shared__ float smf[];
    float* Wp   = smf;
    float* winb = Wp + 8320;
    int tid = threadIdx.x;
    for (int i = tid; i < 128 * 64; i += 256) {
        int k = i >> 6, c = i & 63;
        Wp[(c >> 1) * 260 + (k >> 1) * 4 + ((c & 1) << 1) + (k & 1)] = W[i];
    }
    __syncthreads();
    int lane = tid & 31, wid = tid >> 5;
    float2 bb = ((const float2*)b)[lane];
    float* win = winb + wid * 8 * ND;
    const ulonglong2* wl = (const ulonglong2*)(Wp + (size_t)lane * 260);
    int gw = blockIdx.x * 8 + wid;
    int nw = gridDim.x * 8;
    for (int base = gw * 8; base < NN; base += nw * 8) {
        #pragma unroll
        for (int t = 0; t < 8; t++) {
            float4 v = *(const float4*)(nf + (size_t)(base + t) * ND + lane * 4);
            *(float4*)(win + t * ND + lane * 4) = v;
        }
        __syncwarp();
        ull a0[8], a1[8];
        #pragma unroll
        for (int t = 0; t < 8; t++) { a0[t] = 0ull; a1[t] = 0ull; }
        #pragma unroll 4
        for (int c = 0; c < 32; c++) {
            ulonglong2 wA = wl[2 * c];
            ulonglong2 wB = wl[2 * c + 1];
            #pragma unroll
            for (int t = 0; t < 8; t++) {
                ulonglong2 v = ((const ulonglong2*)(win + t * ND))[c];
                ffma2(a0[t], wA.x, v.x); ffma2(a1[t], wA.y, v.x);
                ffma2(a0[t], wB.x, v.y); ffma2(a1[t], wB.y, v.y);
            }
        }
        #pragma unroll
        for (int t = 0; t < 8; t++) {
            float o0 = fin(a0[t], bb.x);
            float o1 = fin(a1[t], bb.y);
            int n = base + t;
            *(float2*)(g_xb[0] + (size_t)n * H + 2 * lane) = make_float2(o0, o1);
            g_xf[n * 32 + lane] = pack_h2(o0, o1);
        }
        __syncwarp();
    }
}

// ============================================================
// k_con: constraints only; x read from outp (already written)
// ============================================================
__global__ void k_con(const float* __restrict__ W1, const float* __restrict__ b1,
                      const float* __restrict__ w2, const float* __restrict__ b2,
                      const float* __restrict__ xs, float* __restrict__ out) {
    __shared__ float Ws[H * H];
    __shared__ float bs[H];
    __shared__ float w2s[H];
    __shared__ float xb[8][H];
    __shared__ float b2v;
    int tid = threadIdx.x;
    for (int i = tid; i < H * H; i += blockDim.x) Ws[i] = W1[i];
    if (tid < H) { bs[tid] = b1[tid]; w2s[tid] = w2[tid]; }
    if (tid == 0) b2v = b2[0];
    __syncthreads();
    int lane = tid & 31, wid = tid >> 5;
    int gw = blockIdx.x * 8 + wid;
    int nw = gridDim.x * 8;
    for (int n = gw; n < NN; n += nw) {
        float xv0 = xs[(size_t)n * H + lane];
        float xv1 = xs[(size_t)n * H + lane + 32];
        xb[wid][lane]      = xv0;
        xb[wid][lane + 32] = xv1;
        __syncwarp();
        float a0 = bs[lane], a1 = bs[lane + 32];
        #pragma unroll 4
        for (int k = 0; k < H; k++) {
            float v = xb[wid][k];
            a0 += v * Ws[k * H + lane];
            a1 += v * Ws[k * H + lane + 32];
        }
        float p = fmaxf(a0, 0.f) * w2s[lane] + fmaxf(a1, 0.f) * w2s[lane + 32];
        #pragma unroll
        for (int o = 16; o; o >>= 1) p += __shfl_xor_sync(0xffffffffu, p, o);
        if (lane == 0)
            out[(size_t)NN * H + n] = 1.f / (1.f + expf(-(p + b2v)));
        __syncwarp();
    }
}

extern "C" void kernel_launch(void* const* d_in, const int* in_sizes, int n_in,
                              void* d_out, int out_size) {
    const float* nf  = (const float*)d_in[0];
    const float* ef  = (const float*)d_in[1];
    const int*   ei  = (const int*)d_in[2];
    const float* enW = (const float*)d_in[3];
    const float* enb = (const float*)d_in[4];
    const float* eeW = (const float*)d_in[5];
    const float* eeb = (const float*)d_in[6];
    const float* mW1 = (const float*)d_in[7];
    const float* mb1 = (const float*)d_in[8];
    const float* mW2 = (const float*)d_in[9];
    const float* mb2 = (const float*)d_in[10];
    const float* uW1 = (const float*)d_in[11];
    const float* ub1 = (const float*)d_in[12];
    const float* uW2 = (const float*)d_in[13];
    const float* ub2 = (const float*)d_in[14];
    const float* cW1 = (const float*)d_in[15];
    const float* cb1 = (const float*)d_in[16];
    const float* cW2 = (const float*)d_in[17];
    const float* cb2 = (const float*)d_in[18];
    float* out = (float*)d_out;

    int dev = 0, smc = 148;
    cudaGetDevice(&dev);
    cudaDeviceGetAttribute(&smc, cudaDevAttrMultiProcessorCount, dev);

    const int ENN_SMEM = (8320 + 8192) * 4;
    cudaFuncSetAttribute(k_pre,          cudaFuncAttributeMaxDynamicSharedMemorySize, PRE_SMEM);
    cudaFuncSetAttribute(k_msg_mma,      cudaFuncAttributeMaxDynamicSharedMemorySize, MSG_SMEM);
    cudaFuncSetAttribute(k_upd_mma,      cudaFuncAttributeMaxDynamicSharedMemorySize, UPD_SMEM);
    cudaFuncSetAttribute(k_enc_edge_mma, cudaFuncAttributeMaxDynamicSharedMemorySize, ENC_SMEM);
    cudaFuncSetAttribute(k_enc_node,     cudaFuncAttributeMaxDynamicSharedMemorySize, ENN_SMEM);

    k_enc_node<<<smc * 2, 256, ENN_SMEM>>>(nf, enW, enb);
    k_enc_edge_mma<<<smc * 2, 256, ENC_SMEM>>>(ef, eeW, eeb);

    // layer-0 Ps/Pd + agg zero
    k_pre<<<smc * 2, 256, PRE_SMEM>>>(mW1, mb1);

    int cur = 0;
    for (int l = 0; l < 3; l++) {
        k_msg_mma<<<smc * 2, 256, MSG_SMEM>>>(ei,
                                              mW1 + (size_t)l * 192 * H,
                                              mW2 + (size_t)l * H * H, mb2 + l * H);
        int last = (l == 2);
        k_upd_mma<<<smc * 2, 256, UPD_SMEM>>>(uW1 + (size_t)l * 128 * H, ub1 + l * H,
                                              uW2 + (size_t)l * H * H,   ub2 + l * H,
                                              mW1 + (size_t)(l + 1) * 192 * H * (last ? 0 : 1),
                                              mb1 + (l + 1) * H * (last ? 0 : 1),
                                              cur, last ? 0 : 1,
                                              last ? out : nullptr);
        cur = 1 - cur;
    }
    k_con<<<1184, 256>>>(cW1, cb1, cW2, cb2, out, out);
}

// round 17
// speedup vs baseline: 1.6929x; 1.1280x over previous
#include <cuda_runtime.h>
#include <cuda_fp16.h>
#include <math.h>
#include <cstdint>

#define NN 50000
#define NE 800000
#define H  64
#define ND 128

__device__ float g_agg[NN * H];              // PERMUTED cols
__device__ unsigned g_psh[NN * 32];          // Ps fp16 packed, word = tig*8 + nt
__device__ unsigned g_pdh[NN * 32];          // Pd fp16 packed
__device__ unsigned g_et[(size_t)NE * 32];   // e fp16 in MMA A-fragment order
__device__ unsigned g_xf[NN * 32];           // x fp16 (2 cols/word)

__device__ __forceinline__ uint32_t smem_u32(const void* p) {
    uint32_t a;
    asm("{ .reg .u64 t; cvta.to.shared.u64 t, %1; cvt.u32.u64 %0, t; }" : "=r"(a) : "l"(p));
    return a;
}

#define LDSM4(r, addr) \
    asm volatile("ldmatrix.sync.aligned.m8n8.x4.shared.b16 {%0,%1,%2,%3}, [%4];" \
        : "=r"((r)[0]), "=r"((r)[1]), "=r"((r)[2]), "=r"((r)[3]) : "r"(addr))

#define MMA16816(c, a, b0v, b1v) \
    asm volatile("mma.sync.aligned.m16n8k16.row.col.f32.f16.f16.f32 " \
        "{%0,%1,%2,%3},{%4,%5,%6,%7},{%8,%9},{%0,%1,%2,%3};" \
        : "+f"((c)[0]), "+f"((c)[1]), "+f"((c)[2]), "+f"((c)[3]) \
        : "r"((a)[0]), "r"((a)[1]), "r"((a)[2]), "r"((a)[3]), "r"(b0v), "r"(b1v))

__device__ __forceinline__ unsigned pack_h2(float a, float b) {
    __half2 t = __floats2half2_rn(a, b);
    return *reinterpret_cast<unsigned*>(&t);
}
__device__ __forceinline__ float2 h2f(unsigned u) {
    return __half22float2(*reinterpret_cast<__half2*>(&u));
}

// ============================================================
// k_enc_node_mma: x0 = fp16(nf)@W + b (K=128, hi-only) -> g_xf
//   + fused layer-0 Ps/Pd GEMMs + g_agg zeroing
// ============================================================
#define NB 0
#define NS 17408
#define NDD 26624
#define NBIAS 35840
#define NA 36352
#define ENN_SMEM (36352 + 8 * 4352)   // 71168

__global__ void __launch_bounds__(256, 2) k_enc_node_mma(const float* __restrict__ nf,
        const float* __restrict__ W, const float* __restrict__ b,
        const float* __restrict__ nW1, const float* __restrict__ nb1) {
    extern __shared__ char sm[];
    const uint32_t smb = smem_u32(sm);
    int tid = threadIdx.x, lane = tid & 31, wid = tid >> 5;

    for (int i = tid; i < 128 * 64; i += blockDim.x) {
        int k = i >> 6, n = i & 63;
        ((__half*)(sm + NB))[n * 136 + k] = __float2half_rn(W[i]);
    }
    for (int i = tid; i < 64 * 64; i += blockDim.x) {
        int k = i >> 6, n = i & 63;
        ((__half*)(sm + NS))[n * 72 + k]  = __float2half_rn(nW1[k * 64 + n]);
        ((__half*)(sm + NDD))[n * 72 + k] = __float2half_rn(nW1[(128 + k) * 64 + n]);
    }
    if (tid < 64) {
        ((float*)(sm + NBIAS))[tid] = b[tid];
        ((float*)(sm + NBIAS + 256))[tid] = nb1[tid];
    }
    __syncthreads();

    const float* bs   = (const float*)(sm + NBIAS);
    const float* nb1s = (const float*)(sm + NBIAS + 256);
    const int tig = lane & 3, gid = lane >> 2;
    const uint32_t aRow = smb + NA + wid * 4352 + (lane & 15) * 272 + (lane & 16);
    const uint32_t bRow = ((lane & 7) + ((lane & 16) >> 1));
    const uint32_t bAddr = smb + NB + bRow * 272 + (lane & 8) * 2;
    const uint32_t nsH = smb + NS + bRow * 144 + (lane & 8) * 2;
    const uint32_t ndH = smb + NDD + bRow * 144 + (lane & 8) * 2;
    char* aRowPtr = sm + NA + wid * 4352;

    int gw = blockIdx.x * 8 + wid;
    int nw = gridDim.x * 8;
    for (int chunk = gw; chunk < NN / 16; chunk += nw) {
        int base16 = chunk * 16;
        #pragma unroll 4
        for (int t = 0; t < 16; t++) {
            float4 v = *(const float4*)(nf + (size_t)(base16 + t) * ND + lane * 4);
            unsigned* rp = (unsigned*)(aRowPtr + t * 272);
            rp[2 * lane]     = pack_h2(v.x, v.y);
            rp[2 * lane + 1] = pack_h2(v.z, v.w);
        }
        __syncwarp();

        float acc[8][4];
        #pragma unroll
        for (int n = 0; n < 8; n++)
            #pragma unroll
            for (int j = 0; j < 4; j++) acc[n][j] = 0.f;

        #pragma unroll 2
        for (int kt = 0; kt < 8; kt++) {
            uint32_t ah[4];
            LDSM4(ah, aRow + kt * 32);
            #pragma unroll
            for (int ng = 0; ng < 4; ng++) {
                uint32_t bh[4];
                LDSM4(bh, bAddr + ng * 16 * 272 + kt * 32);
                MMA16816(acc[2 * ng],     ah, bh[0], bh[1]);
                MMA16816(acc[2 * ng + 1], ah, bh[2], bh[3]);
            }
        }

        int n0 = base16 + gid, n1 = base16 + gid + 8;
        uint32_t a2x[4][4];
        #pragma unroll
        for (int nt = 0; nt < 8; nt++) {
            float2 bb = *(const float2*)(bs + nt * 8 + 2 * tig);
            int c = nt * 8 + 2 * tig;
            unsigned w0 = pack_h2(acc[nt][0] + bb.x, acc[nt][1] + bb.y);
            unsigned w1 = pack_h2(acc[nt][2] + bb.x, acc[nt][3] + bb.y);
            g_xf[n0 * 32 + nt * 4 + tig] = w0;
            g_xf[n1 * 32 + nt * 4 + tig] = w1;
            a2x[nt >> 1][2 * (nt & 1)]     = w0;
            a2x[nt >> 1][2 * (nt & 1) + 1] = w1;
            *(float2*)(g_agg + (size_t)n0 * H + c) = make_float2(0.f, 0.f);
            *(float2*)(g_agg + (size_t)n1 * H + c) = make_float2(0.f, 0.f);
        }

        // fused layer-0 Ps/Pd
        float as[8][4];
        unsigned w0[8], w1[8];
        #pragma unroll
        for (int n = 0; n < 8; n++)
            #pragma unroll
            for (int j = 0; j < 4; j++) as[n][j] = 0.f;
        #pragma unroll
        for (int kt = 0; kt < 4; kt++)
            #pragma unroll
            for (int ng = 0; ng < 4; ng++) {
                uint32_t bh[4];
                LDSM4(bh, nsH + ng * 16 * 144 + kt * 32);
                MMA16816(as[2 * ng],     a2x[kt], bh[0], bh[1]);
                MMA16816(as[2 * ng + 1], a2x[kt], bh[2], bh[3]);
            }
        #pragma unroll
        for (int nt = 0; nt < 8; nt++) {
            float2 bb = *(const float2*)(nb1s + nt * 8 + 2 * tig);
            w0[nt] = pack_h2(as[nt][0] + bb.x, as[nt][1] + bb.y);
            w1[nt] = pack_h2(as[nt][2] + bb.x, as[nt][3] + bb.y);
        }
        *(uint4*)(g_psh + n0 * 32 + tig * 8)     = make_uint4(w0[0], w0[1], w0[2], w0[3]);
        *(uint4*)(g_psh + n0 * 32 + tig * 8 + 4) = make_uint4(w0[4], w0[5], w0[6], w0[7]);
        *(uint4*)(g_psh + n1 * 32 + tig * 8)     = make_uint4(w1[0], w1[1], w1[2], w1[3]);
        *(uint4*)(g_psh + n1 * 32 + tig * 8 + 4) = make_uint4(w1[4], w1[5], w1[6], w1[7]);

        #pragma unroll
        for (int n = 0; n < 8; n++)
            #pragma unroll
            for (int j = 0; j < 4; j++) as[n][j] = 0.f;
        #pragma unroll
        for (int kt = 0; kt < 4; kt++)
            #pragma unroll
            for (int ng = 0; ng < 4; ng++) {
                uint32_t bh[4];
                LDSM4(bh, ndH + ng * 16 * 144 + kt * 32);
                MMA16816(as[2 * ng],     a2x[kt], bh[0], bh[1]);
                MMA16816(as[2 * ng + 1], a2x[kt], bh[2], bh[3]);
            }
        #pragma unroll
        for (int nt = 0; nt < 8; nt++) {
            w0[nt] = pack_h2(as[nt][0], as[nt][1]);
            w1[nt] = pack_h2(as[nt][2], as[nt][3]);
        }
        *(uint4*)(g_pdh + n0 * 32 + tig * 8)     = make_uint4(w0[0], w0[1], w0[2], w0[3]);
        *(uint4*)(g_pdh + n0 * 32 + tig * 8 + 4) = make_uint4(w0[4], w0[5], w0[6], w0[7]);
        *(uint4*)(g_pdh + n1 * 32 + tig * 8)     = make_uint4(w1[0], w1[1], w1[2], w1[3]);
        *(uint4*)(g_pdh + n1 * 32 + tig * 8 + 4) = make_uint4(w1[4], w1[5], w1[6], w1[7]);
        __syncwarp();
    }
}

// ============================================================
// k_msg_mma: unchanged (verified R14-R16)
// ============================================================
#define MB1H 0
#define MB2H 9216
#define MBIAS 18432
#define MSG_SMEM 18944

__global__ void __launch_bounds__(256, 2) k_msg_mma(const int* __restrict__ ei,
        const float* __restrict__ W1, const float* __restrict__ W2,
        const float* __restrict__ b2) {
    extern __shared__ char sm[];
    const uint32_t smb = smem_u32(sm);
    int tid = threadIdx.x, lane = tid & 31, wid = tid >> 5;

    for (int i = tid; i < 64 * 64; i += blockDim.x) {
        int k = i >> 6, n = i & 63;
        ((__half*)(sm + MB1H))[n * 72 + k] = __float2half_rn(W1[(64 + k) * 64 + n]);
        ((__half*)(sm + MB2H))[n * 72 + k] = __float2half_rn(W2[k * 64 + n]);
    }
    if (tid < 64) ((float*)(sm + MBIAS))[tid] = b2[tid];
    __syncthreads();

    const float* b2s = (const float*)(sm + MBIAS);
    const int tig = lane & 3, gid = lane >> 2;
    const uint32_t bRow  = ((lane & 7) + ((lane & 16) >> 1));
    const uint32_t b1H = smb + MB1H + bRow * 144 + (lane & 8) * 2;
    const uint32_t b2H = smb + MB2H + bRow * 144 + (lane & 8) * 2;

    const uint4* et4 = (const uint4*)g_et;
    const int NCH = NE / 16;
    int gw = blockIdx.x * 8 + wid;
    int nw = gridDim.x * 8;

    for (int chunk = gw; chunk < NCH; chunk += nw) {
        int base16 = chunk * 16;
        int s = 0, d = 0;
        if (lane < 16) { s = ei[base16 + lane]; d = ei[NE + base16 + lane]; }
        int s0 = __shfl_sync(0xffffffffu, s, gid), s1 = __shfl_sync(0xffffffffu, s, gid + 8);
        int d0 = __shfl_sync(0xffffffffu, d, gid), d1 = __shfl_sync(0xffffffffu, d, gid + 8);

        uint4 A[4];
        #pragma unroll
        for (int kt = 0; kt < 4; kt++)
            A[kt] = __ldg(et4 + (size_t)chunk * 128 + kt * 32 + lane);

        float acc[8][4];
        #pragma unroll
        for (int n = 0; n < 8; n++)
            #pragma unroll
            for (int j = 0; j < 4; j++) acc[n][j] = 0.f;

        #pragma unroll
        for (int kt = 0; kt < 4; kt++) {
            uint32_t ah[4] = {A[kt].x, A[kt].y, A[kt].z, A[kt].w};
            #pragma unroll
            for (int ng = 0; ng < 4; ng++) {
                uint32_t bh[4];
                LDSM4(bh, b1H + ng * 16 * 144 + kt * 32);
                MMA16816(acc[2 * ng],     ah, bh[0], bh[1]);
                MMA16816(acc[2 * ng + 1], ah, bh[2], bh[3]);
            }
        }

        unsigned P0w[8], P1w[8], Q0w[8], Q1w[8];
        {
            const uint4* p0 = (const uint4*)(g_psh + s0 * 32 + tig * 8);
            const uint4* p1 = (const uint4*)(g_psh + s1 * 32 + tig * 8);
            const uint4* q0 = (const uint4*)(g_pdh + d0 * 32 + tig * 8);
            const uint4* q1 = (const uint4*)(g_pdh + d1 * 32 + tig * 8);
            uint4 a, b;
            a = __ldg(p0); b = __ldg(p0 + 1);
            P0w[0]=a.x; P0w[1]=a.y; P0w[2]=a.z; P0w[3]=a.w;
            P0w[4]=b.x; P0w[5]=b.y; P0w[6]=b.z; P0w[7]=b.w;
            a = __ldg(p1); b = __ldg(p1 + 1);
            P1w[0]=a.x; P1w[1]=a.y; P1w[2]=a.z; P1w[3]=a.w;
            P1w[4]=b.x; P1w[5]=b.y; P1w[6]=b.z; P1w[7]=b.w;
            a = __ldg(q0); b = __ldg(q0 + 1);
            Q0w[0]=a.x; Q0w[1]=a.y; Q0w[2]=a.z; Q0w[3]=a.w;
            Q0w[4]=b.x; Q0w[5]=b.y; Q0w[6]=b.z; Q0w[7]=b.w;
            a = __ldg(q1); b = __ldg(q1 + 1);
            Q1w[0]=a.x; Q1w[1]=a.y; Q1w[2]=a.z; Q1w[3]=a.w;
            Q1w[4]=b.x; Q1w[5]=b.y; Q1w[6]=b.z; Q1w[7]=b.w;
        }

        float acc2[8][4];
        #pragma unroll
        for (int n = 0; n < 8; n++)
            #pragma unroll
            for (int j = 0; j < 4; j++) acc2[n][j] = 0.f;

        #pragma unroll
        for (int kt = 0; kt < 4; kt++) {
            uint32_t a2[4];
            #pragma unroll
            for (int j = 0; j < 2; j++) {
                int nt = 2 * kt + j;
                float2 p0v = h2f(P0w[nt]), q0v = h2f(Q0w[nt]);
                float2 p1v = h2f(P1w[nt]), q1v = h2f(Q1w[nt]);
                float v0 = fmaxf(acc[nt][0] + p0v.x + q0v.x, 0.f);
                float v1 = fmaxf(acc[nt][1] + p0v.y + q0v.y, 0.f);
                float v2 = fmaxf(acc[nt][2] + p1v.x + q1v.x, 0.f);
                float v3 = fmaxf(acc[nt][3] + p1v.y + q1v.y, 0.f);
                a2[2 * j]     = pack_h2(v0, v1);
                a2[2 * j + 1] = pack_h2(v2, v3);
            }
            #pragma unroll
            for (int ng = 0; ng < 4; ng++) {
                uint32_t bh[4];
                LDSM4(bh, b2H + ng * 16 * 144 + kt * 32);
                MMA16816(acc2[2 * ng],     a2, bh[0], bh[1]);
                MMA16816(acc2[2 * ng + 1], a2, bh[2], bh[3]);
            }
        }

        float* plo = g_agg + (size_t)d0 * H + tig * 4;
        float* phi = g_agg + (size_t)d1 * H + tig * 4;
        #pragma unroll
        for (int m = 0; m < 4; m++) {
            float2 be = *(const float2*)(b2s + (2 * m) * 8 + 2 * tig);
            float2 bo = *(const float2*)(b2s + (2 * m + 1) * 8 + 2 * tig);
            float e0 = acc2[2 * m][0] + be.x, e1 = acc2[2 * m][1] + be.y;
            float o0 = acc2[2 * m + 1][0] + bo.x, o1 = acc2[2 * m + 1][1] + bo.y;
            asm volatile("red.global.add.v4.f32 [%0], {%1,%2,%3,%4};"
                :: "l"(plo + m * 16), "f"(e0), "f"(e1), "f"(o0), "f"(o1) : "memory");
            float e2 = acc2[2 * m][2] + be.x, e3 = acc2[2 * m][3] + be.y;
            float o2 = acc2[2 * m + 1][2] + bo.x, o3 = acc2[2 * m + 1][3] + bo.y;
            asm volatile("red.global.add.v4.f32 [%0], {%1,%2,%3,%4};"
                :: "l"(phi + m * 16), "f"(e2), "f"(e3), "f"(o2), "f"(o3) : "memory");
        }
        __syncwarp();
    }
}

// ============================================================
// k_upd_mma: fused next-layer Ps/Pd (do_pre) OR fused
//            constraint head + fp32 x output (last)
// ============================================================
#define UB1H 0
#define UB2H 17408
#define UNW1S 26624
#define UNW1D 35840
#define UBIAS 45056
#define UA 46112
#define UPD_SMEM (46112 + 8 * 4352)   // 80928

__global__ void __launch_bounds__(256, 2) k_upd_mma(
        const float* __restrict__ W1, const float* __restrict__ b1,
        const float* __restrict__ W2, const float* __restrict__ b2,
        const float* __restrict__ nW1, const float* __restrict__ nb1,
        const float* __restrict__ cW1, const float* __restrict__ cb1,
        const float* __restrict__ cW2, const float* __restrict__ cb2,
        int do_pre, int last, float* __restrict__ outp) {
    extern __shared__ char sm[];
    const uint32_t smb = smem_u32(sm);
    int tid = threadIdx.x, lane = tid & 31, wid = tid >> 5;

    for (int i = tid; i < 128 * 64; i += blockDim.x) {
        int k = i >> 6, n = i & 63;
        ((__half*)(sm + UB1H))[n * 136 + k] = __float2half_rn(W1[i]);
    }
    for (int i = tid; i < 64 * 64; i += blockDim.x) {
        int k = i >> 6, n = i & 63;
        ((__half*)(sm + UB2H))[n * 72 + k] = __float2half_rn(W2[i]);
        if (do_pre) {
            ((__half*)(sm + UNW1S))[n * 72 + k] = __float2half_rn(nW1[k * 64 + n]);
            ((__half*)(sm + UNW1D))[n * 72 + k] = __float2half_rn(nW1[(128 + k) * 64 + n]);
        } else if (last) {
            ((__half*)(sm + UNW1S))[n * 72 + k] = __float2half_rn(cW1[i]);
        }
    }
    if (tid < 64) {
        ((float*)(sm + UBIAS))[tid] = b1[tid];
        ((float*)(sm + UBIAS + 256))[tid] = b2[tid];
        ((float*)(sm + UBIAS + 512))[tid] = do_pre ? nb1[tid] : (last ? cb1[tid] : 0.f);
        ((float*)(sm + UBIAS + 768))[tid] = last ? cW2[tid] : 0.f;
    }
    if (tid == 0) *((float*)(sm + UBIAS + 1024)) = last ? cb2[0] : 0.f;
    __syncthreads();

    const float* b1s = (const float*)(sm + UBIAS);
    const float* b2s = (const float*)(sm + UBIAS + 256);
    const float* xb1s = (const float*)(sm + UBIAS + 512);   // nb1 or cb1
    const float* cw2s = (const float*)(sm + UBIAS + 768);
    const float cb2v = *((const float*)(sm + UBIAS + 1024));

    const int tig = lane & 3, gid = lane >> 2;
    const int wagg = (2 * (lane >> 3) + (lane & 1)) * 4 + ((lane >> 1) & 3);
    const uint32_t aRow = smb + UA + wid * 4352 + (lane & 15) * 272 + (lane & 16);
    const uint32_t bRow  = ((lane & 7) + ((lane & 16) >> 1));
    const uint32_t b1AddrH = smb + UB1H + bRow * 272 + (lane & 8) * 2;
    const uint32_t b2AddrH = smb + UB2H + bRow * 144 + (lane & 8) * 2;
    const uint32_t nsH = smb + UNW1S + bRow * 144 + (lane & 8) * 2;
    const uint32_t ndH = smb + UNW1D + bRow * 144 + (lane & 8) * 2;
    char* aRowPtr = sm + UA + wid * 4352;

    int gw = blockIdx.x * 8 + wid;
    int nw = gridDim.x * 8;
    for (int chunk = gw; chunk < NN / 16; chunk += nw) {
        int base16 = chunk * 16;
        #pragma unroll 4
        for (int t = 0; t < 16; t++) {
            int n = base16 + t;
            float2* agp = (float2*)(g_agg + (size_t)n * H) + lane;
            float2 ag = *agp;
            *agp = make_float2(0.f, 0.f);
            char* rp = aRowPtr + t * 272;
            ((unsigned*)rp)[lane]         = g_xf[n * 32 + lane];
            ((unsigned*)(rp + 128))[wagg] = pack_h2(ag.x, ag.y);
        }
        __syncwarp();

        float acc[8][4];
        #pragma unroll
        for (int n = 0; n < 8; n++)
            #pragma unroll
            for (int j = 0; j < 4; j++) acc[n][j] = 0.f;

        #pragma unroll 2
        for (int kt = 0; kt < 8; kt++) {
            uint32_t ah[4];
            LDSM4(ah, aRow + kt * 32);
            #pragma unroll
            for (int ng = 0; ng < 4; ng++) {
                uint32_t bh[4];
                LDSM4(bh, b1AddrH + ng * 16 * 272 + kt * 32);
                MMA16816(acc[2 * ng],     ah, bh[0], bh[1]);
                MMA16816(acc[2 * ng + 1], ah, bh[2], bh[3]);
            }
        }

        float acc2[8][4];
        #pragma unroll
        for (int n = 0; n < 8; n++)
            #pragma unroll
            for (int j = 0; j < 4; j++) acc2[n][j] = 0.f;

        #pragma unroll
        for (int kt = 0; kt < 4; kt++) {
            uint32_t a2[4];
            #pragma unroll
            for (int j = 0; j < 2; j++) {
                int nt = kt * 2 + j;
                float2 bb = *(const float2*)(b1s + nt * 8 + 2 * tig);
                float v0 = fmaxf(acc[nt][0] + bb.x, 0.f);
                float v1 = fmaxf(acc[nt][1] + bb.y, 0.f);
                float v2 = fmaxf(acc[nt][2] + bb.x, 0.f);
                float v3 = fmaxf(acc[nt][3] + bb.y, 0.f);
                a2[2 * j]     = pack_h2(v0, v1);
                a2[2 * j + 1] = pack_h2(v2, v3);
            }
            #pragma unroll
            for (int ng = 0; ng < 4; ng++) {
                uint32_t bh[4];
                LDSM4(bh, b2AddrH + ng * 16 * 144 + kt * 32);
                MMA16816(acc2[2 * ng],     a2, bh[0], bh[1]);
                MMA16816(acc2[2 * ng + 1], a2, bh[2], bh[3]);
            }
        }

        int n0 = base16 + gid, n1 = base16 + gid + 8;
        uint32_t a2x[4][4];
        #pragma unroll
        for (int nt = 0; nt < 8; nt++) {
            float2 bb = *(const float2*)(b2s + nt * 8 + 2 * tig);
            float f0 = acc2[nt][0] + bb.x, f1 = acc2[nt][1] + bb.y;
            float f2 = acc2[nt][2] + bb.x, f3 = acc2[nt][3] + bb.y;
            if (last) {
                *(float2*)(outp + (size_t)n0 * H + nt * 8 + 2 * tig) = make_float2(f0, f1);
                *(float2*)(outp + (size_t)n1 * H + nt * 8 + 2 * tig) = make_float2(f2, f3);
            }
            unsigned w0 = pack_h2(f0, f1);
            unsigned w1 = pack_h2(f2, f3);
            g_xf[n0 * 32 + nt * 4 + tig] = w0;
            g_xf[n1 * 32 + nt * 4 + tig] = w1;
            a2x[nt >> 1][2 * (nt & 1)]     = w0;
            a2x[nt >> 1][2 * (nt & 1) + 1] = w1;
        }

        if (do_pre) {
            float as[8][4];
            unsigned w0[8], w1[8];
            #pragma unroll
            for (int n = 0; n < 8; n++)
                #pragma unroll
                for (int j = 0; j < 4; j++) as[n][j] = 0.f;
            #pragma unroll
            for (int kt = 0; kt < 4; kt++)
                #pragma unroll
                for (int ng = 0; ng < 4; ng++) {
                    uint32_t bh[4];
                    LDSM4(bh, nsH + ng * 16 * 144 + kt * 32);
                    MMA16816(as[2 * ng],     a2x[kt], bh[0], bh[1]);
                    MMA16816(as[2 * ng + 1], a2x[kt], bh[2], bh[3]);
                }
            #pragma unroll
            for (int nt = 0; nt < 8; nt++) {
                float2 bb = *(const float2*)(xb1s + nt * 8 + 2 * tig);
                w0[nt] = pack_h2(as[nt][0] + bb.x, as[nt][1] + bb.y);
                w1[nt] = pack_h2(as[nt][2] + bb.x, as[nt][3] + bb.y);
            }
            *(uint4*)(g_psh + n0 * 32 + tig * 8)     = make_uint4(w0[0], w0[1], w0[2], w0[3]);
            *(uint4*)(g_psh + n0 * 32 + tig * 8 + 4) = make_uint4(w0[4], w0[5], w0[6], w0[7]);
            *(uint4*)(g_psh + n1 * 32 + tig * 8)     = make_uint4(w1[0], w1[1], w1[2], w1[3]);
            *(uint4*)(g_psh + n1 * 32 + tig * 8 + 4) = make_uint4(w1[4], w1[5], w1[6], w1[7]);

            #pragma unroll
            for (int n = 0; n < 8; n++)
                #pragma unroll
                for (int j = 0; j < 4; j++) as[n][j] = 0.f;
            #pragma unroll
            for (int kt = 0; kt < 4; kt++)
                #pragma unroll
                for (int ng = 0; ng < 4; ng++) {
                    uint32_t bh[4];
                    LDSM4(bh, ndH + ng * 16 * 144 + kt * 32);
                    MMA16816(as[2 * ng],     a2x[kt], bh[0], bh[1]);
                    MMA16816(as[2 * ng + 1], a2x[kt], bh[2], bh[3]);
                }
            #pragma unroll
            for (int nt = 0; nt < 8; nt++) {
                w0[nt] = pack_h2(as[nt][0], as[nt][1]);
                w1[nt] = pack_h2(as[nt][2], as[nt][3]);
            }
            *(uint4*)(g_pdh + n0 * 32 + tig * 8)     = make_uint4(w0[0], w0[1], w0[2], w0[3]);
            *(uint4*)(g_pdh + n0 * 32 + tig * 8 + 4) = make_uint4(w0[4], w0[5], w0[6], w0[7]);
            *(uint4*)(g_pdh + n1 * 32 + tig * 8)     = make_uint4(w1[0], w1[1], w1[2], w1[3]);
            *(uint4*)(g_pdh + n1 * 32 + tig * 8 + 4) = make_uint4(w1[4], w1[5], w1[6], w1[7]);
        } else if (last) {
            // fused constraint head: h = relu(x@cW1+cb1); p = h@cW2 + cb2
            float as[8][4];
            #pragma unroll
            for (int n = 0; n < 8; n++)
                #pragma unroll
                for (int j = 0; j < 4; j++) as[n][j] = 0.f;
            #pragma unroll
            for (int kt = 0; kt < 4; kt++)
                #pragma unroll
                for (int ng = 0; ng < 4; ng++) {
                    uint32_t bh[4];
                    LDSM4(bh, nsH + ng * 16 * 144 + kt * 32);
                    MMA16816(as[2 * ng],     a2x[kt], bh[0], bh[1]);
                    MMA16816(as[2 * ng + 1], a2x[kt], bh[2], bh[3]);
                }
            float p0 = 0.f, p1 = 0.f;
            #pragma unroll
            for (int nt = 0; nt < 8; nt++) {
                float2 cb = *(const float2*)(xb1s + nt * 8 + 2 * tig);
                float2 cw = *(const float2*)(cw2s + nt * 8 + 2 * tig);
                p0 += fmaxf(as[nt][0] + cb.x, 0.f) * cw.x + fmaxf(as[nt][1] + cb.y, 0.f) * cw.y;
                p1 += fmaxf(as[nt][2] + cb.x, 0.f) * cw.x + fmaxf(as[nt][3] + cb.y, 0.f) * cw.y;
            }
            p0 += __shfl_xor_sync(0xffffffffu, p0, 1);
            p0 += __shfl_xor_sync(0xffffffffu, p0, 2);
            p1 += __shfl_xor_sync(0xffffffffu, p1, 1);
            p1 += __shfl_xor_sync(0xffffffffu, p1, 2);
            if (tig == 0) {
                outp[(size_t)NN * H + n0] = 1.f / (1.f + expf(-(p0 + cb2v)));
                outp[(size_t)NN * H + n1] = 1.f / (1.f + expf(-(p1 + cb2v)));
            }
        }
        __syncwarp();
    }
}

// ============================================================
// k_enc_edge_mma: unchanged (verified R15-R16)
// ============================================================
#define EBH 0
#define EBIAS 9216
#define EA 9472
#define ENC_SMEM (9472 + 8 * 2304)

__global__ void __launch_bounds__(256) k_enc_edge_mma(const float* __restrict__ ef,
        const float* __restrict__ W, const float* __restrict__ b) {
    extern __shared__ char sm[];
    const uint32_t smb = smem_u32(sm);
    int tid = threadIdx.x, lane = tid & 31, wid = tid >> 5;

    for (int i = tid; i < 64 * 64; i += blockDim.x) {
        int k = i >> 6, n = i & 63;
        ((__half*)(sm + EBH))[n * 72 + k] = __float2half_rn(W[i]);
    }
    if (tid < 64) ((float*)(sm + EBIAS))[tid] = b[tid];
    __syncthreads();

    const float* bs = (const float*)(sm + EBIAS);
    const int tig = lane & 3;
    const int gi = lane >> 2;
    const uint32_t aRow = smb + EA + wid * 2304 + (lane & 15) * 144 + (lane & 16);
    const uint32_t bRow  = ((lane & 7) + ((lane & 16) >> 1));
    const uint32_t bAddrH = smb + EBH + bRow * 144 + (lane & 8) * 2;
    char* aRowPtr = sm + EA + wid * 2304;

    int gw = blockIdx.x * 8 + wid;
    int nw = gridDim.x * 8;
    for (int chunk = gw; chunk < NE / 16; chunk += nw) {
        int base16 = chunk * 16;
        #pragma unroll 4
        for (int t = 0; t < 16; t++) {
            float2 v = ((const float2*)(ef + (size_t)(base16 + t) * H))[lane];
            ((unsigned*)(aRowPtr + t * 144))[lane] = pack_h2(v.x, v.y);
        }
        __syncwarp();

        float acc[8][4];
        #pragma unroll
        for (int n = 0; n < 8; n++)
            #pragma unroll
            for (int j = 0; j < 4; j++) acc[n][j] = 0.f;

        #pragma unroll
        for (int kt = 0; kt < 4; kt++) {
            uint32_t ah[4];
            LDSM4(ah, aRow + kt * 32);
            #pragma unroll
            for (int ng = 0; ng < 4; ng++) {
                uint32_t bh[4];
                LDSM4(bh, bAddrH + ng * 16 * 144 + kt * 32);
                MMA16816(acc[2 * ng],     ah, bh[0], bh[1]);
                MMA16816(acc[2 * ng + 1], ah, bh[2], bh[3]);
            }
        }

        unsigned* de = g_et + (size_t)chunk * 512;
        #pragma unroll
        for (int nt = 0; nt < 8; nt++) {
            float2 bb = *(const float2*)(bs + nt * 8 + 2 * tig);
            float f0 = acc[nt][0] + bb.x, f1 = acc[nt][1] + bb.y;
            float f2 = acc[nt][2] + bb.x, f3 = acc[nt][3] + bb.y;
            int idx = (nt >> 1) * 128 + (gi * 4 + tig) * 4 + 2 * (nt & 1);
            de[idx]     = pack_h2(f0, f1);
            de[idx + 1] = pack_h2(f2, f3);
        }
        __syncwarp();
    }
}

extern "C" void kernel_launch(void* const* d_in, const int* in_sizes, int n_in,
                              void* d_out, int out_size) {
    const float* nf  = (const float*)d_in[0];
    const float* ef  = (const float*)d_in[1];
    const int*   ei  = (const int*)d_in[2];
    const float* enW = (const float*)d_in[3];
    const float* enb = (const float*)d_in[4];
    const float* eeW = (const float*)d_in[5];
    const float* eeb = (const float*)d_in[6];
    const float* mW1 = (const float*)d_in[7];
    const float* mb1 = (const float*)d_in[8];
    const float* mW2 = (const float*)d_in[9];
    const float* mb2 = (const float*)d_in[10];
    const float* uW1 = (const float*)d_in[11];
    const float* ub1 = (const float*)d_in[12];
    const float* uW2 = (const float*)d_in[13];
    const float* ub2 = (const float*)d_in[14];
    const float* cW1 = (const float*)d_in[15];
    const float* cb1 = (const float*)d_in[16];
    const float* cW2 = (const float*)d_in[17];
    const float* cb2 = (const float*)d_in[18];
    float* out = (float*)d_out;

    int dev = 0, smc = 148;
    cudaGetDevice(&dev);
    cudaDeviceGetAttribute(&smc, cudaDevAttrMultiProcessorCount, dev);

    cudaFuncSetAttribute(k_enc_node_mma, cudaFuncAttributeMaxDynamicSharedMemorySize, ENN_SMEM);
    cudaFuncSetAttribute(k_msg_mma,      cudaFuncAttributeMaxDynamicSharedMemorySize, MSG_SMEM);
    cudaFuncSetAttribute(k_upd_mma,      cudaFuncAttributeMaxDynamicSharedMemorySize, UPD_SMEM);
    cudaFuncSetAttribute(k_enc_edge_mma, cudaFuncAttributeMaxDynamicSharedMemorySize, ENC_SMEM);

    k_enc_edge_mma<<<smc * 2, 256, ENC_SMEM>>>(ef, eeW, eeb);
    k_enc_node_mma<<<smc * 2, 256, ENN_SMEM>>>(nf, enW, enb, mW1, mb1);

    for (int l = 0; l < 3; l++) {
        k_msg_mma<<<smc * 2, 256, MSG_SMEM>>>(ei,
                                              mW1 + (size_t)l * 192 * H,
                                              mW2 + (size_t)l * H * H, mb2 + l * H);
        int last = (l == 2);
        k_upd_mma<<<smc * 2, 256, UPD_SMEM>>>(uW1 + (size_t)l * 128 * H, ub1 + l * H,
                                              uW2 + (size_t)l * H * H,   ub2 + l * H,
                                              mW1 + (size_t)(l + 1) * 192 * H * (last ? 0 : 1),
                                              mb1 + (l + 1) * H * (last ? 0 : 1),
                                              cW1, cb1, cW2, cb2,
                                              last ? 0 : 1, last,
                                              last ? out : nullptr);
    }
}